// round 15
// baseline (speedup 1.0000x reference)
#include <cuda_runtime.h>
#include <stdint.h>
#include <math.h>

#define B_   4
#define N_   4096
#define DIM_ 512
#define H_   8
#define DH_  64
#define M_   256
#define BH_  32

// ---------------- scratch ----------------------------------------------------
__device__ float g_wo [H_*DH_*DIM_];
__device__ float g_q  [BH_*N_*DH_];
__device__ float g_k  [BH_*N_*DH_];
__device__ float g_v  [BH_*N_*DH_];
__device__ float g_qlm[BH_*M_*DH_];
__device__ float g_klm[BH_*M_*DH_];
__device__ float g_s1 [BH_*N_*M_];
__device__ float g_a2 [BH_*M_*M_];
__device__ float g_s3 [BH_*M_*N_];
__device__ float g_z  [BH_*M_*M_];
__device__ float g_z2 [BH_*M_*M_];
__device__ float g_xz [BH_*M_*M_];
__device__ float g_t1 [BH_*M_*M_];
__device__ float g_t3 [BH_*M_*M_];
__device__ float g_t5 [BH_*M_*M_];
__device__ float g_a3v[BH_*M_*DH_];
__device__ float g_zv [BH_*M_*DH_];
__device__ float g_of [B_*N_*DIM_];
__device__ float g_part[4*BH_*M_*DH_];
__device__ float g_gmax[2];

// ---------------- tf32 helpers -----------------------------------------------
__device__ __forceinline__ uint32_t f2tf(float f) {
    uint32_t u; asm("cvt.rna.tf32.f32 %0, %1;" : "=r"(u) : "f"(f)); return u;
}
__device__ __forceinline__ float rtf(float f) { return __uint_as_float(f2tf(f)); }
__device__ __forceinline__ uint32_t tfbits(uint32_t raw) {
    return f2tf(__uint_as_float(raw));
}

__device__ __forceinline__ void mma_tf32(float c[4],
    uint32_t a0, uint32_t a1, uint32_t a2, uint32_t a3, uint32_t b0, uint32_t b1)
{
    asm("mma.sync.aligned.m16n8k8.row.col.f32.tf32.tf32.f32 "
        "{%0,%1,%2,%3}, {%4,%5,%6,%7}, {%8,%9}, {%0,%1,%2,%3};"
        : "+f"(c[0]), "+f"(c[1]), "+f"(c[2]), "+f"(c[3])
        : "r"(a0), "r"(a1), "r"(a2), "r"(a3), "r"(b0), "r"(b1));
}

__device__ __forceinline__ void ldsm_x4(uint32_t addr, uint32_t r[4]) {
    asm volatile("ldmatrix.sync.aligned.m8n8.x4.b16 {%0,%1,%2,%3}, [%4];"
        : "=r"(r[0]), "=r"(r[1]), "=r"(r[2]), "=r"(r[3]) : "r"(addr));
}

__device__ __forceinline__ void cp16(uint32_t smem, const void* gmem) {
    asm volatile("cp.async.cg.shared.global [%0], [%1], 16;\n"
                 :: "r"(smem), "l"(gmem));
}
__device__ __forceinline__ void cp_commit() {
    asm volatile("cp.async.commit_group;\n" ::: "memory");
}
template<int N>
__device__ __forceinline__ void cp_waitg() {
    asm volatile("cp.async.wait_group %0;\n" :: "n"(N) : "memory");
}

// ---------------- pre-round inputs ---------------------------------------------
__global__ void round_copy(const float* __restrict__ in, float* __restrict__ out)
{
    long long t = (long long)blockIdx.x * 256 + threadIdx.x;
    out[t] = rtf(in[t]);
}

// ---------------- tensor-core batched GEMM (cp.async + ldmatrix fragments) -----
// MODE: 0: alpha*acc   2: dval*I - acc   3: C=acc, C2=dval*I-acc
//       4: acc + bias[col] (not rounded)  5: qkv scatter (q scaled 0.125)
//       6: ACCUMULATE into [b,n,h,d] 'of' layout   7: fused row softmax (WGM=1)
// CVTIN: apply tf32 rounding at fragment load (inputs may be raw fp32)
template<int BM, int BN, int WGM, int WGN, int TRANSB, int MODE,
         int BK = 16, int STAGES = 4, int SPLITK = 1, int RND = 1, int CVTIN = 0>
__global__ void __launch_bounds__(256, 2)
gemm_tc(int K,
        const float* __restrict__ A,  int lda, long long sA,
        const float* __restrict__ Bg, int ldb, long long sB,
        float* __restrict__ C, int ldc, long long sC,
        float alpha, float dval,
        float* __restrict__ C2, const float* __restrict__ bias,
        float* __restrict__ oq, float* __restrict__ okk, float* __restrict__ ov,
        int colOff)
{
    constexpr int WM = BM / WGM, WN = BN / WGN;
    constexpr int MI = WM / 16,  NI = WN / 8;
    constexpr int NSTEP = BK / 8;
    constexpr int SAW = BK + 4;
    constexpr int SBW = TRANSB ? (BK + 4) : (BN + 8);
    constexpr int ASZ = BM * SAW;
    constexpr int BSZ = TRANSB ? (BN * SAW) : (BK * SBW);
    constexpr int STW = ASZ + BSZ;
    constexpr int CPR = BK / 4;
    constexpr int RPI = 256 / CPR;
    constexpr int A_IT  = BM / RPI;
    constexpr int B1_IT = BN / RPI;
    constexpr int NB4   = BN / 4;
    constexpr int B0_RS = 256 / NB4;
    constexpr int B0_IT = BK / B0_RS;

    extern __shared__ __align__(16) float dyn[];
    float* red = dyn + STAGES * STW;

    const int bz = blockIdx.z;
    const int bh = bz / SPLITK, ks = bz % SPLITK;
    A  += (long long)bh * sA + (long long)ks * K;
    Bg += (long long)bh * sB + (TRANSB ? (long long)ks * K
                                       : (long long)ks * K * ldb);
    if (MODE != 5 && MODE != 6) C += (long long)bz * sC;
    if (MODE == 3) C2 += (long long)bz * sC;

    const int tid = threadIdx.x;
    const int rowBase = blockIdx.y * BM;
    const int colBase = blockIdx.x * BN + colOff;
    const int w = tid >> 5, lane = tid & 31;
    const int wm = w / WGN, wn = w % WGN;
    const int tm = lane >> 2, lq = lane & 3;
    const int lrow = lane & 15;
    const int lhi  = (lane >> 4) & 1;

    float acc[MI][NI][4];
#pragma unroll
    for (int mi = 0; mi < MI; mi++)
#pragma unroll
        for (int ni = 0; ni < NI; ni++)
#pragma unroll
            for (int r = 0; r < 4; r++) acc[mi][ni][r] = 0.f;

    const int a_r = tid / CPR, a_c = (tid % CPR) * 4;
    const int b0k = tid / NB4, b0n = (tid % NB4) * 4;

    const uint32_t dynb = (uint32_t)__cvta_generic_to_shared(dyn);

    auto LOADG = [&](int kt, int buf) {
        uint32_t sa = dynb + buf * (STW * 4);
        uint32_t sb = sa + ASZ * 4;
#pragma unroll
        for (int i = 0; i < A_IT; i++) {
            int r = a_r + RPI * i;
            cp16(sa + (r * SAW + a_c) * 4,
                 A + (long long)(rowBase + r) * lda + kt + a_c);
        }
        if (TRANSB == 0) {
#pragma unroll
            for (int i = 0; i < B0_IT; i++) {
                int k = b0k + B0_RS * i;
                cp16(sb + (k * SBW + b0n) * 4,
                     Bg + (long long)(kt + k) * ldb + colBase + b0n);
            }
        } else {
#pragma unroll
            for (int i = 0; i < B1_IT; i++) {
                int r = a_r + RPI * i;
                cp16(sb + (r * SAW + a_c) * 4,
                     Bg + (long long)(colBase + r) * ldb + kt + a_c);
            }
        }
    };

    auto LDF = [&](uint32_t sa, uint32_t sb, const float* Bs, int kk,
                   uint32_t (*af)[4], uint32_t (*bf)[2]) {
#pragma unroll
        for (int mi = 0; mi < MI; mi++) {
            uint32_t a = sa + (uint32_t)(((wm * WM + mi * 16 + lrow) * SAW + kk) << 2)
                            + (lhi << 4);
            ldsm_x4(a, af[mi]);
            if (CVTIN) {
#pragma unroll
                for (int j = 0; j < 4; j++) af[mi][j] = tfbits(af[mi][j]);
            }
        }
        if (TRANSB == 1) {
#pragma unroll
            for (int p = 0; p < NI / 2; p++) {
                uint32_t b = sb + (uint32_t)(((wn * WN + p * 16 + lrow) * SAW + kk) << 2)
                                + (lhi << 4);
                uint32_t r[4];
                ldsm_x4(b, r);
                if (CVTIN) {
#pragma unroll
                    for (int j = 0; j < 4; j++) r[j] = tfbits(r[j]);
                }
                bf[2 * p][0]     = r[0];
                bf[2 * p + 1][0] = r[1];
                bf[2 * p][1]     = r[2];
                bf[2 * p + 1][1] = r[3];
            }
        } else {
            const int kq = kk + lq;
#pragma unroll
            for (int ni = 0; ni < NI; ni++) {
                int n = wn * WN + ni * 8 + tm;
                if (CVTIN) {
                    bf[ni][0] = f2tf(Bs[ kq      * SBW + n]);
                    bf[ni][1] = f2tf(Bs[(kq + 4) * SBW + n]);
                } else {
                    bf[ni][0] = __float_as_uint(Bs[ kq      * SBW + n]);
                    bf[ni][1] = __float_as_uint(Bs[(kq + 4) * SBW + n]);
                }
            }
        }
    };

    auto MMAS = [&](uint32_t (*af)[4], uint32_t (*bf)[2]) {
#pragma unroll
        for (int mi = 0; mi < MI; mi++)
#pragma unroll
            for (int ni = 0; ni < NI; ni++)
                mma_tf32(acc[mi][ni], af[mi][0], af[mi][1], af[mi][2], af[mi][3],
                         bf[ni][0], bf[ni][1]);
    };

    const int T = K / BK;
#pragma unroll
    for (int s = 0; s < STAGES - 1; s++) { LOADG(s * BK, s); cp_commit(); }

    for (int t = 0; t < T; t++) {
        cp_waitg<STAGES - 2>();
        __syncthreads();
        if (t + STAGES - 1 < T) LOADG((t + STAGES - 1) * BK, (t + STAGES - 1) % STAGES);
        cp_commit();

        const uint32_t sa = dynb + (t % STAGES) * (STW * 4);
        const uint32_t sb = sa + ASZ * 4;
        const float* Bs = dyn + (t % STAGES) * STW + ASZ;

        uint32_t af0[MI][4], bf0[NI][2], af1[MI][4], bf1[NI][2];
        LDF(sa, sb, Bs, 0, af0, bf0);
#pragma unroll
        for (int s = 0; s < NSTEP; s++) {
            if (s + 1 < NSTEP) {
                if ((s & 1) == 0) LDF(sa, sb, Bs, (s + 1) * 8, af1, bf1);
                else              LDF(sa, sb, Bs, (s + 1) * 8, af0, bf0);
            }
            if ((s & 1) == 0) MMAS(af0, bf0);
            else              MMAS(af1, bf1);
        }
        __syncthreads();
    }

    if (MODE == 7) {
        float rmax[MI][2], rsum[MI][2];
#pragma unroll
        for (int mi = 0; mi < MI; mi++)
#pragma unroll
            for (int half = 0; half < 2; half++) {
                float m = -3.4e38f;
#pragma unroll
                for (int ni = 0; ni < NI; ni++)
                    m = fmaxf(m, fmaxf(acc[mi][ni][2 * half], acc[mi][ni][2 * half + 1]));
                m = fmaxf(m, __shfl_xor_sync(~0u, m, 1));
                m = fmaxf(m, __shfl_xor_sync(~0u, m, 2));
                rmax[mi][half] = m;
            }
        if (lq == 0) {
#pragma unroll
            for (int mi = 0; mi < MI; mi++)
#pragma unroll
                for (int half = 0; half < 2; half++)
                    red[(mi * 16 + tm + 8 * half) * WGN + w] = rmax[mi][half];
        }
        __syncthreads();
#pragma unroll
        for (int mi = 0; mi < MI; mi++)
#pragma unroll
            for (int half = 0; half < 2; half++) {
                float m = -3.4e38f;
#pragma unroll
                for (int ww = 0; ww < WGN; ww++)
                    m = fmaxf(m, red[(mi * 16 + tm + 8 * half) * WGN + ww]);
                rmax[mi][half] = m;
            }
        __syncthreads();
#pragma unroll
        for (int mi = 0; mi < MI; mi++)
#pragma unroll
            for (int half = 0; half < 2; half++) {
                float s = 0.f;
#pragma unroll
                for (int ni = 0; ni < NI; ni++) {
                    float e0 = __expf(acc[mi][ni][2 * half]     - rmax[mi][half]);
                    float e1 = __expf(acc[mi][ni][2 * half + 1] - rmax[mi][half]);
                    acc[mi][ni][2 * half]     = e0;
                    acc[mi][ni][2 * half + 1] = e1;
                    s += e0 + e1;
                }
                s += __shfl_xor_sync(~0u, s, 1);
                s += __shfl_xor_sync(~0u, s, 2);
                rsum[mi][half] = s;
            }
        if (lq == 0) {
#pragma unroll
            for (int mi = 0; mi < MI; mi++)
#pragma unroll
                for (int half = 0; half < 2; half++)
                    red[(mi * 16 + tm + 8 * half) * WGN + w] = rsum[mi][half];
        }
        __syncthreads();
#pragma unroll
        for (int mi = 0; mi < MI; mi++)
#pragma unroll
            for (int half = 0; half < 2; half++) {
                float s = 0.f;
#pragma unroll
                for (int ww = 0; ww < WGN; ww++)
                    s += red[(mi * 16 + tm + 8 * half) * WGN + ww];
                rsum[mi][half] = 1.f / s;
            }
#pragma unroll
        for (int mi = 0; mi < MI; mi++) {
#pragma unroll
            for (int ni = 0; ni < NI; ni++) {
                int c = colBase + wn * WN + ni * 8 + 2 * lq;
#pragma unroll
                for (int half = 0; half < 2; half++) {
                    int r = rowBase + mi * 16 + tm + 8 * half;
                    float2 v = make_float2(rtf(acc[mi][ni][2 * half] * rsum[mi][half]),
                                           rtf(acc[mi][ni][2 * half + 1] * rsum[mi][half]));
                    *(float2*)&C[(long long)r * ldc + c] = v;
                }
            }
        }
        return;
    }

#pragma unroll
    for (int mi = 0; mi < MI; mi++) {
        int rBase = rowBase + wm * WM + mi * 16 + tm;
#pragma unroll
        for (int ni = 0; ni < NI; ni++) {
            int c = colBase + wn * WN + ni * 8 + 2 * lq;
#pragma unroll
            for (int half = 0; half < 2; half++) {
                int r = rBase + 8 * half;
                float2 v = make_float2(acc[mi][ni][2 * half], acc[mi][ni][2 * half + 1]);
                if (MODE == 0) {
                    v.x *= alpha; v.y *= alpha;
                    if (RND) { v.x = rtf(v.x); v.y = rtf(v.y); }
                    *(float2*)&C[(long long)r * ldc + c] = v;
                } else if (MODE == 2) {
                    v.x = (r == c     ? dval : 0.f) - v.x;
                    v.y = (r == c + 1 ? dval : 0.f) - v.y;
                    if (RND) { v.x = rtf(v.x); v.y = rtf(v.y); }
                    *(float2*)&C[(long long)r * ldc + c] = v;
                } else if (MODE == 3) {
                    float2 v1 = v;
                    if (RND) { v1.x = rtf(v1.x); v1.y = rtf(v1.y); }
                    *(float2*)&C[(long long)r * ldc + c] = v1;
                    float2 v2;
                    v2.x = (r == c     ? dval : 0.f) - v.x;
                    v2.y = (r == c + 1 ? dval : 0.f) - v.y;
                    if (RND) { v2.x = rtf(v2.x); v2.y = rtf(v2.y); }
                    *(float2*)&C2[(long long)r * ldc + c] = v2;
                } else if (MODE == 4) {
                    v.x += bias[c]; v.y += bias[c + 1];
                    *(float2*)&C[(long long)r * ldc + c] = v;
                } else if (MODE == 5) {
                    int b = r >> 12, n = r & 4095;
                    int part = c >> 9, h = (c >> 6) & 7, d = c & 63;
                    if (part == 0) { v.x *= 0.125f; v.y *= 0.125f; }
                    v.x = rtf(v.x); v.y = rtf(v.y);
                    float* dst = (part == 0) ? oq : ((part == 1) ? okk : ov);
                    *(float2*)&dst[((((long long)(b * 8 + h)) << 12) + n) * 64 + d] = v;
                } else { // 6: accumulate onto conv already in 'of'
                    int b = bz >> 3, h = bz & 7;
                    long long oidx = ((long long)(b * 4096 + r)) * 512 + h * 64 + c;
                    float2 prev = *(float2*)&C[oidx];
                    v.x = rtf(v.x + prev.x);
                    v.y = rtf(v.y + prev.y);
                    *(float2*)&C[oidx] = v;
                }
            }
        }
    }
}

static inline int smem_bytes(int BM, int BN, int TRANSB, int MODE, int WGN,
                             int BK, int STAGES) {
    int ASZ = BM * (BK + 4);
    int BSZ = TRANSB ? BN * (BK + 4) : BK * (BN + 8);
    int b = STAGES * (ASZ + BSZ) * 4;
    if (MODE == 7) b += BM * WGN * 4;
    return b;
}

// ---------------- split-K reduction ----------------------------------------------
__global__ void reduce4(const float* __restrict__ p, float* __restrict__ out)
{
    long long t = (long long)blockIdx.x * 256 + threadIdx.x;
    int bh = (int)(t >> 14);
    int e  = (int)(t & 16383);
    const float* pp = p + ((long long)bh * 4) * 16384 + e;
    out[t] = rtf(pp[0] + pp[16384] + pp[2 * 16384] + pp[3 * 16384]);
}

// ---------------- landmarks ---------------------------------------------------
__global__ void landmarks_kernel(const float* __restrict__ q, const float* __restrict__ k,
                                 float* __restrict__ qlm, float* __restrict__ klm)
{
    int idx = blockIdx.x;
    int d = threadIdx.x;
    long long base = ((long long)idx * 16) * 64 + d;
    float sq = 0.f, sk = 0.f;
#pragma unroll
    for (int j = 0; j < 16; j++) {
        sq += q[base + j * 64];
        sk += k[base + j * 64];
    }
    qlm[(long long)idx * 64 + d] = rtf(sq * 0.0625f);
    klm[(long long)idx * 64 + d] = rtf(sk * 0.0625f);
}

// ---------------- softmax 4096 ----------------------------------------------------
__global__ void softmax4096(float* __restrict__ data)
{
    __shared__ float redm[8], reds[8];
    float4* p = (float4*)(data + ((long long)blockIdx.x << 12));
    int tid = threadIdx.x;
    float4 v[4];
#pragma unroll
    for (int i = 0; i < 4; i++) v[i] = p[tid + 256 * i];
    float m = -3.4e38f;
#pragma unroll
    for (int i = 0; i < 4; i++)
        m = fmaxf(m, fmaxf(fmaxf(v[i].x, v[i].y), fmaxf(v[i].z, v[i].w)));
#pragma unroll
    for (int s = 16; s; s >>= 1) m = fmaxf(m, __shfl_xor_sync(~0u, m, s));
    if ((tid & 31) == 0) redm[tid >> 5] = m;
    __syncthreads();
#pragma unroll
    for (int j = 0; j < 8; j++) m = fmaxf(m, redm[j]);

    float sum = 0.f;
#pragma unroll
    for (int i = 0; i < 4; i++) {
        v[i].x = __expf(v[i].x - m); v[i].y = __expf(v[i].y - m);
        v[i].z = __expf(v[i].z - m); v[i].w = __expf(v[i].w - m);
        sum += v[i].x + v[i].y + v[i].z + v[i].w;
    }
#pragma unroll
    for (int s = 16; s; s >>= 1) sum += __shfl_xor_sync(~0u, sum, s);
    if ((tid & 31) == 0) reds[tid >> 5] = sum;
    __syncthreads();
    sum = 0.f;
#pragma unroll
    for (int j = 0; j < 8; j++) sum += reds[j];
    float inv = 1.f / sum;
#pragma unroll
    for (int i = 0; i < 4; i++) {
        v[i].x = rtf(v[i].x * inv); v[i].y = rtf(v[i].y * inv);
        v[i].z = rtf(v[i].z * inv); v[i].w = rtf(v[i].w * inv);
        p[tid + 256 * i] = v[i];
    }
}

// ---------------- pinv init ----------------------------------------------------
__global__ void zero_gmax(float* gm) { gm[0] = 0.f; gm[1] = 0.f; }

__global__ void pinv_scales(const float* __restrict__ a, float* gm)
{
    __shared__ float red[256];
    int bh = blockIdx.x, tid = threadIdx.x;
    const float* A = a + ((long long)bh << 16);
    float rs = 0.f;
    for (int j = 0; j < 256; j++) rs += fabsf(A[tid * 256 + j]);
    red[tid] = rs; __syncthreads();
    for (int s = 128; s > 0; s >>= 1) {
        if (tid < s) red[tid] = fmaxf(red[tid], red[tid + s]);
        __syncthreads();
    }
    if (tid == 0) atomicMax((int*)&gm[0], __float_as_int(red[0]));
    __syncthreads();
    float cs = 0.f;
    for (int i = 0; i < 256; i++) cs += fabsf(A[i * 256 + tid]);
    red[tid] = cs; __syncthreads();
    for (int s = 128; s > 0; s >>= 1) {
        if (tid < s) red[tid] = fmaxf(red[tid], red[tid + s]);
        __syncthreads();
    }
    if (tid == 0) atomicMax((int*)&gm[1], __float_as_int(red[0]));
}

__global__ void pinv_init(const float* __restrict__ a, float* __restrict__ z,
                          const float* __restrict__ gm)
{
    long long t = (long long)blockIdx.x * 256 + threadIdx.x;
    int bh = (int)(t >> 16);
    int ij = (int)(t & 65535);
    int i = ij >> 8, j = ij & 255;
    float inv = 1.f / (gm[0] * gm[1]);
    z[((long long)bh << 16) + ij] = rtf(a[((long long)bh << 16) + (j << 8) + i] * inv);
}

// ---------------- depthwise conv (writes 'of'; MODE 6 accumulates) -------------
__global__ void conv_of(const float* __restrict__ v, const float* __restrict__ w,
                        float* __restrict__ of)
{
    long long t = (long long)blockIdx.x * 256 + threadIdx.x;
    int d = (int)(t & 63);
    long long r = t >> 6;
    int n  = (int)(r & 4095);
    int bh = (int)(r >> 12);
    int h  = bh & 7, b = bh >> 3;
    const float* vp = v + ((long long)bh << 18) + d;
    float s = 0.f;
#pragma unroll
    for (int tp = 0; tp < 33; tp++) {
        int nn = n + tp - 16;
        if (nn >= 0 && nn < 4096)
            s = fmaf(vp[(long long)nn << 6], w[h * 33 + tp], s);
    }
    of[((long long)(b * 4096 + n)) * 512 + h * 64 + d] = s;
}

// ---------------- host orchestration -------------------------------------------
extern "C" void kernel_launch(void* const* d_in, const int* in_sizes, int n_in,
                              void* d_out, int out_size)
{
    const float* x    = (const float*)d_in[0];
    const float* Wqkv = (const float*)d_in[1];
    const float* Wout = (const float*)d_in[2];
    const float* bout = (const float*)d_in[3];
    const float* rk   = (const float*)d_in[4];
    float* yout = (float*)d_out;

    float *wo, *q, *k, *v, *qlm, *klm, *s1, *a2, *s3, *z, *z2, *xz,
          *t1, *t3, *t5, *a3v, *zv, *of, *part, *gm;
    cudaGetSymbolAddress((void**)&wo,  g_wo);
    cudaGetSymbolAddress((void**)&q,   g_q);
    cudaGetSymbolAddress((void**)&k,   g_k);
    cudaGetSymbolAddress((void**)&v,   g_v);
    cudaGetSymbolAddress((void**)&qlm, g_qlm);
    cudaGetSymbolAddress((void**)&klm, g_klm);
    cudaGetSymbolAddress((void**)&s1,  g_s1);
    cudaGetSymbolAddress((void**)&a2,  g_a2);
    cudaGetSymbolAddress((void**)&s3,  g_s3);
    cudaGetSymbolAddress((void**)&z,   g_z);
    cudaGetSymbolAddress((void**)&z2,  g_z2);
    cudaGetSymbolAddress((void**)&xz,  g_xz);
    cudaGetSymbolAddress((void**)&t1,  g_t1);
    cudaGetSymbolAddress((void**)&t3,  g_t3);
    cudaGetSymbolAddress((void**)&t5,  g_t5);
    cudaGetSymbolAddress((void**)&a3v, g_a3v);
    cudaGetSymbolAddress((void**)&zv,  g_zv);
    cudaGetSymbolAddress((void**)&of,  g_of);
    cudaGetSymbolAddress((void**)&part,g_part);
    cudaGetSymbolAddress((void**)&gm,  g_gmax);

    const long long sQ  = (long long)N_ * DH_;
    const long long sLM = (long long)M_ * DH_;
    const long long sS1 = (long long)N_ * M_;
    const long long sMM = (long long)M_ * M_;

    const int smQKV = smem_bytes(128,128,0,5,4,32,3);
    const int smSM  = smem_bytes(64,256,1,7,8,16,4);
    const int smS3  = smem_bytes(128,128,1,0,4,16,4);
    const int smNS  = smem_bytes(64,128,0,0,8,32,3);   // NS: 64x128 tiles
    const int sm64  = smem_bytes(128,64,0,0,2,32,3);
    const int smFP  = smem_bytes(128,128,0,4,4,32,3);

    static cudaStream_t sB = nullptr, sC = nullptr;
    static cudaEvent_t evF = nullptr, evC = nullptr, evV = nullptr, evJ = nullptr;
    static bool attr_done = false;
    if (!attr_done) {
        cudaFuncSetAttribute(gemm_tc<128,128,2,4,0,5,32,3,1,1,1>, cudaFuncAttributeMaxDynamicSharedMemorySize, smQKV);
        cudaFuncSetAttribute(gemm_tc<64,256,1,8,1,7,16,4>,  cudaFuncAttributeMaxDynamicSharedMemorySize, smSM);
        cudaFuncSetAttribute(gemm_tc<128,128,2,4,1,0,16,4,1,0>, cudaFuncAttributeMaxDynamicSharedMemorySize, smS3);
        cudaFuncSetAttribute(gemm_tc<64,128,1,8,0,3,32,3>, cudaFuncAttributeMaxDynamicSharedMemorySize, smNS);
        cudaFuncSetAttribute(gemm_tc<64,128,1,8,0,2,32,3>, cudaFuncAttributeMaxDynamicSharedMemorySize, smNS);
        cudaFuncSetAttribute(gemm_tc<64,128,1,8,0,0,32,3>, cudaFuncAttributeMaxDynamicSharedMemorySize, smNS);
        cudaFuncSetAttribute(gemm_tc<128,64,4,2,0,0,32,3,4,0>, cudaFuncAttributeMaxDynamicSharedMemorySize, sm64);
        cudaFuncSetAttribute(gemm_tc<128,64,4,2,0,0,32,3>, cudaFuncAttributeMaxDynamicSharedMemorySize, sm64);
        cudaFuncSetAttribute(gemm_tc<128,64,4,2,0,6,32,3>, cudaFuncAttributeMaxDynamicSharedMemorySize, sm64);
        cudaFuncSetAttribute(gemm_tc<128,128,2,4,0,4,32,3>, cudaFuncAttributeMaxDynamicSharedMemorySize, smFP);
        cudaStreamCreateWithFlags(&sB, cudaStreamNonBlocking);
        cudaStreamCreateWithFlags(&sC, cudaStreamNonBlocking);
        cudaEventCreateWithFlags(&evF, cudaEventDisableTiming);
        cudaEventCreateWithFlags(&evC, cudaEventDisableTiming);
        cudaEventCreateWithFlags(&evV, cudaEventDisableTiming);
        cudaEventCreateWithFlags(&evJ, cudaEventDisableTiming);
        attr_done = true;
    }

    // 1a. qkv part A: q,k columns (0..1023) — CVTIN reads raw x/Wqkv (no pre-round)
    gemm_tc<128,128,2,4,0,5,32,3,1,1,1><<<dim3(8, 128, 1), 256, smQKV>>>(
        512, x, 512, 0, Wqkv, 1536, 0,
        nullptr, 0, 0, 1.f, 0.f, nullptr, nullptr, q, k, v, 0);

    // 1b. qkv part B: v columns — overlapped on stream C
    cudaEventRecord(evC, 0);
    cudaStreamWaitEvent(sC, evC, 0);
    gemm_tc<128,128,2,4,0,5,32,3,1,1,1><<<dim3(4, 128, 1), 256, smQKV, sC>>>(
        512, x, 512, 0, Wqkv, 1536, 0,
        nullptr, 0, 0, 1.f, 0.f, nullptr, nullptr, q, k, v, 1024);
    cudaEventRecord(evV, sC);

    // 2. landmarks (needs q,k only)
    landmarks_kernel<<<BH_ * M_, DH_>>>(q, k, qlm, klm);

    // 3. attn2 (NS branch depends only on it)
    gemm_tc<64,256,1,8,1,7,16,4><<<dim3(1, 4, BH_), 256, smSM>>>(
        64, qlm, 64, sLM, klm, 64, sLM,
        a2, 256, sMM, 1.f, 0.f, nullptr, nullptr, nullptr, nullptr, nullptr, 0);

    // ---- fork: side stream B runs pinv + Newton-Schulz (64x128 tiles, 256 CTAs)
    cudaEventRecord(evF, 0);
    cudaStreamWaitEvent(sB, evF, 0);

    zero_gmax<<<1, 1, 0, sB>>>(gm);
    pinv_scales<<<BH_, 256, 0, sB>>>(a2, gm);
    pinv_init<<<(BH_ * M_ * M_) / 256, 256, 0, sB>>>(a2, z, gm);

    float* za = z;
    float* zb = z2;
    for (int it = 0; it < 6; it++) {
        gemm_tc<64,128,1,8,0,3,32,3><<<dim3(2, 4, BH_), 256, smNS, sB>>>(
            256, a2, 256, sMM, za, 256, sMM,
            xz, 256, sMM, 1.f, 7.f, t1, nullptr, nullptr, nullptr, nullptr, 0);
        gemm_tc<64,128,1,8,0,2,32,3><<<dim3(2, 4, BH_), 256, smNS, sB>>>(
            256, xz, 256, sMM, t1, 256, sMM,
            t3, 256, sMM, 1.f, 15.f, nullptr, nullptr, nullptr, nullptr, nullptr, 0);
        gemm_tc<64,128,1,8,0,2,32,3><<<dim3(2, 4, BH_), 256, smNS, sB>>>(
            256, xz, 256, sMM, t3, 256, sMM,
            t5, 256, sMM, 1.f, 13.f, nullptr, nullptr, nullptr, nullptr, nullptr, 0);
        gemm_tc<64,128,1,8,0,0,32,3><<<dim3(2, 4, BH_), 256, smNS, sB>>>(
            256, za, 256, sMM, t5, 256, sMM,
            zb, 256, sMM, 0.25f, 0.f, nullptr, nullptr, nullptr, nullptr, nullptr, 0);
        float* sw = za; za = zb; zb = sw;
    }
    cudaEventRecord(evJ, sB);

    // ---- main stream: independent attention branch ----
    round_copy<<<(H_*DH_*DIM_) / 256, 256>>>(Wout, wo);

    gemm_tc<64,256,1,8,1,7,16,4><<<dim3(1, 64, BH_), 256, smSM>>>(
        64, q, 64, sQ, klm, 64, sLM,
        s1, 256, sS1, 1.f, 0.f, nullptr, nullptr, nullptr, nullptr, nullptr, 0);

    gemm_tc<128,128,2,4,1,0,16,4,1,0><<<dim3(32, 2, BH_), 256, smS3>>>(
        64, qlm, 64, sLM, k, 64, sQ,
        s3, 4096, (long long)M_ * N_, 1.f, 0.f, nullptr, nullptr, nullptr, nullptr, nullptr, 0);
    softmax4096<<<BH_ * M_, 256>>>(s3);

    // v-consumers wait on qkv part B
    cudaStreamWaitEvent(0, evV, 0);

    conv_of<<<(BH_ * N_ * DH_) / 256, 256>>>(v, rk, of);

    gemm_tc<128,64,4,2,0,0,32,3,4,0><<<dim3(1, 2, BH_ * 4), 256, sm64>>>(
        1024, s3, 4096, (long long)M_ * N_, v, 64, sQ,
        part, 64, sLM, 1.f, 0.f, nullptr, nullptr, nullptr, nullptr, nullptr, 0);
    reduce4<<<(BH_ * M_ * DH_) / 256, 256>>>(part, a3v);

    // ---- join with NS ----
    cudaStreamWaitEvent(0, evJ, 0);

    gemm_tc<128,64,4,2,0,0,32,3><<<dim3(1, 2, BH_), 256, sm64>>>(
        256, z, 256, sMM, a3v, 64, sLM,
        zv, 64, sLM, 1.f, 0.f, nullptr, nullptr, nullptr, nullptr, nullptr, 0);

    gemm_tc<128,64,4,2,0,6,32,3><<<dim3(1, 32, BH_), 256, sm64>>>(
        256, s1, 256, sS1, zv, 64, sLM,
        of, 0, 0, 1.f, 0.f, nullptr, nullptr, nullptr, nullptr, nullptr, 0);

    gemm_tc<128,128,2,4,0,4,32,3><<<dim3(4, 128, 1), 256, smFP>>>(
        512, of, 512, 0, wo, 512, 0,
        yout, 512, 0, 1.f, 0.f, nullptr, bout, nullptr, nullptr, nullptr, 0);
}

// round 16
// speedup vs baseline: 1.0082x; 1.0082x over previous
#include <cuda_runtime.h>
#include <stdint.h>
#include <math.h>

#define B_   4
#define N_   4096
#define DIM_ 512
#define H_   8
#define DH_  64
#define M_   256
#define BH_  32

// ---------------- scratch ----------------------------------------------------
__device__ float g_q  [BH_*N_*DH_];
__device__ float g_k  [BH_*N_*DH_];
__device__ float g_v  [BH_*N_*DH_];
__device__ float g_qlm[BH_*M_*DH_];
__device__ float g_klm[BH_*M_*DH_];
__device__ float g_s1 [BH_*N_*M_];
__device__ float g_a2 [BH_*M_*M_];
__device__ float g_s3 [BH_*M_*N_];
__device__ float g_z  [BH_*M_*M_];
__device__ float g_z2 [BH_*M_*M_];
__device__ float g_xz [BH_*M_*M_];
__device__ float g_t1 [BH_*M_*M_];
__device__ float g_t3 [BH_*M_*M_];
__device__ float g_t5 [BH_*M_*M_];
__device__ float g_a3v[BH_*M_*DH_];
__device__ float g_zv [BH_*M_*DH_];
__device__ float g_of [B_*N_*DIM_];
__device__ float g_part[4*BH_*M_*DH_];
__device__ float g_gmax[2];

// ---------------- tf32 helpers -----------------------------------------------
__device__ __forceinline__ uint32_t f2tf(float f) {
    uint32_t u; asm("cvt.rna.tf32.f32 %0, %1;" : "=r"(u) : "f"(f)); return u;
}
__device__ __forceinline__ float rtf(float f) { return __uint_as_float(f2tf(f)); }
__device__ __forceinline__ uint32_t tfbits(uint32_t raw) {
    return f2tf(__uint_as_float(raw));
}

__device__ __forceinline__ void mma_tf32(float c[4],
    uint32_t a0, uint32_t a1, uint32_t a2, uint32_t a3, uint32_t b0, uint32_t b1)
{
    asm("mma.sync.aligned.m16n8k8.row.col.f32.tf32.tf32.f32 "
        "{%0,%1,%2,%3}, {%4,%5,%6,%7}, {%8,%9}, {%0,%1,%2,%3};"
        : "+f"(c[0]), "+f"(c[1]), "+f"(c[2]), "+f"(c[3])
        : "r"(a0), "r"(a1), "r"(a2), "r"(a3), "r"(b0), "r"(b1));
}

__device__ __forceinline__ void ldsm_x4(uint32_t addr, uint32_t r[4]) {
    asm volatile("ldmatrix.sync.aligned.m8n8.x4.b16 {%0,%1,%2,%3}, [%4];"
        : "=r"(r[0]), "=r"(r[1]), "=r"(r[2]), "=r"(r[3]) : "r"(addr));
}

__device__ __forceinline__ void cp16(uint32_t smem, const void* gmem) {
    asm volatile("cp.async.cg.shared.global [%0], [%1], 16;\n"
                 :: "r"(smem), "l"(gmem));
}
__device__ __forceinline__ void cp_commit() {
    asm volatile("cp.async.commit_group;\n" ::: "memory");
}
template<int N>
__device__ __forceinline__ void cp_waitg() {
    asm volatile("cp.async.wait_group %0;\n" :: "n"(N) : "memory");
}

// ---------------- tensor-core batched GEMM (cp.async + ldmatrix fragments) -----
// MODE: 0: alpha*acc   2: dval*I - acc   3: C=acc, C2=dval*I-acc
//       4: acc + bias[col] (not rounded)  5: qkv scatter (q scaled 0.125)
//       6: ACCUMULATE into [b,n,h,d] 'of' layout   7: fused row softmax (WGM=1)
// CVTIN: apply tf32 rounding at fragment load (inputs may be raw fp32)
template<int BM, int BN, int WGM, int WGN, int TRANSB, int MODE,
         int BK = 16, int STAGES = 4, int SPLITK = 1, int RND = 1, int CVTIN = 0>
__global__ void __launch_bounds__(256, 2)
gemm_tc(int K,
        const float* __restrict__ A,  int lda, long long sA,
        const float* __restrict__ Bg, int ldb, long long sB,
        float* __restrict__ C, int ldc, long long sC,
        float alpha, float dval,
        float* __restrict__ C2, const float* __restrict__ bias,
        float* __restrict__ oq, float* __restrict__ okk, float* __restrict__ ov,
        int colOff)
{
    constexpr int WM = BM / WGM, WN = BN / WGN;
    constexpr int MI = WM / 16,  NI = WN / 8;
    constexpr int NSTEP = BK / 8;
    constexpr int SAW = BK + 4;
    constexpr int SBW = TRANSB ? (BK + 4) : (BN + 8);
    constexpr int ASZ = BM * SAW;
    constexpr int BSZ = TRANSB ? (BN * SAW) : (BK * SBW);
    constexpr int STW = ASZ + BSZ;
    constexpr int CPR = BK / 4;
    constexpr int RPI = 256 / CPR;
    constexpr int A_IT  = BM / RPI;
    constexpr int B1_IT = BN / RPI;
    constexpr int NB4   = BN / 4;
    constexpr int B0_RS = 256 / NB4;
    constexpr int B0_IT = BK / B0_RS;

    extern __shared__ __align__(16) float dyn[];
    float* red = dyn + STAGES * STW;

    const int bz = blockIdx.z;
    const int bh = bz / SPLITK, ks = bz % SPLITK;
    A  += (long long)bh * sA + (long long)ks * K;
    Bg += (long long)bh * sB + (TRANSB ? (long long)ks * K
                                       : (long long)ks * K * ldb);
    if (MODE != 5 && MODE != 6) C += (long long)bz * sC;
    if (MODE == 3) C2 += (long long)bz * sC;

    const int tid = threadIdx.x;
    const int rowBase = blockIdx.y * BM;
    const int colBase = blockIdx.x * BN + colOff;
    const int w = tid >> 5, lane = tid & 31;
    const int wm = w / WGN, wn = w % WGN;
    const int tm = lane >> 2, lq = lane & 3;
    const int lrow = lane & 15;
    const int lhi  = (lane >> 4) & 1;

    float acc[MI][NI][4];
#pragma unroll
    for (int mi = 0; mi < MI; mi++)
#pragma unroll
        for (int ni = 0; ni < NI; ni++)
#pragma unroll
            for (int r = 0; r < 4; r++) acc[mi][ni][r] = 0.f;

    const int a_r = tid / CPR, a_c = (tid % CPR) * 4;
    const int b0k = tid / NB4, b0n = (tid % NB4) * 4;

    const uint32_t dynb = (uint32_t)__cvta_generic_to_shared(dyn);

    auto LOADG = [&](int kt, int buf) {
        uint32_t sa = dynb + buf * (STW * 4);
        uint32_t sb = sa + ASZ * 4;
#pragma unroll
        for (int i = 0; i < A_IT; i++) {
            int r = a_r + RPI * i;
            cp16(sa + (r * SAW + a_c) * 4,
                 A + (long long)(rowBase + r) * lda + kt + a_c);
        }
        if (TRANSB == 0) {
#pragma unroll
            for (int i = 0; i < B0_IT; i++) {
                int k = b0k + B0_RS * i;
                cp16(sb + (k * SBW + b0n) * 4,
                     Bg + (long long)(kt + k) * ldb + colBase + b0n);
            }
        } else {
#pragma unroll
            for (int i = 0; i < B1_IT; i++) {
                int r = a_r + RPI * i;
                cp16(sb + (r * SAW + a_c) * 4,
                     Bg + (long long)(colBase + r) * ldb + kt + a_c);
            }
        }
    };

    auto LDF = [&](uint32_t sa, uint32_t sb, const float* Bs, int kk,
                   uint32_t (*af)[4], uint32_t (*bf)[2]) {
#pragma unroll
        for (int mi = 0; mi < MI; mi++) {
            uint32_t a = sa + (uint32_t)(((wm * WM + mi * 16 + lrow) * SAW + kk) << 2)
                            + (lhi << 4);
            ldsm_x4(a, af[mi]);
            if (CVTIN) {
#pragma unroll
                for (int j = 0; j < 4; j++) af[mi][j] = tfbits(af[mi][j]);
            }
        }
        if (TRANSB == 1) {
#pragma unroll
            for (int p = 0; p < NI / 2; p++) {
                uint32_t b = sb + (uint32_t)(((wn * WN + p * 16 + lrow) * SAW + kk) << 2)
                                + (lhi << 4);
                uint32_t r[4];
                ldsm_x4(b, r);
                if (CVTIN) {
#pragma unroll
                    for (int j = 0; j < 4; j++) r[j] = tfbits(r[j]);
                }
                bf[2 * p][0]     = r[0];
                bf[2 * p + 1][0] = r[1];
                bf[2 * p][1]     = r[2];
                bf[2 * p + 1][1] = r[3];
            }
        } else {
            const int kq = kk + lq;
#pragma unroll
            for (int ni = 0; ni < NI; ni++) {
                int n = wn * WN + ni * 8 + tm;
                if (CVTIN) {
                    bf[ni][0] = f2tf(Bs[ kq      * SBW + n]);
                    bf[ni][1] = f2tf(Bs[(kq + 4) * SBW + n]);
                } else {
                    bf[ni][0] = __float_as_uint(Bs[ kq      * SBW + n]);
                    bf[ni][1] = __float_as_uint(Bs[(kq + 4) * SBW + n]);
                }
            }
        }
    };

    auto MMAS = [&](uint32_t (*af)[4], uint32_t (*bf)[2]) {
#pragma unroll
        for (int mi = 0; mi < MI; mi++)
#pragma unroll
            for (int ni = 0; ni < NI; ni++)
                mma_tf32(acc[mi][ni], af[mi][0], af[mi][1], af[mi][2], af[mi][3],
                         bf[ni][0], bf[ni][1]);
    };

    const int T = K / BK;
#pragma unroll
    for (int s = 0; s < STAGES - 1; s++) { LOADG(s * BK, s); cp_commit(); }

    for (int t = 0; t < T; t++) {
        cp_waitg<STAGES - 2>();
        __syncthreads();
        if (t + STAGES - 1 < T) LOADG((t + STAGES - 1) * BK, (t + STAGES - 1) % STAGES);
        cp_commit();

        const uint32_t sa = dynb + (t % STAGES) * (STW * 4);
        const uint32_t sb = sa + ASZ * 4;
        const float* Bs = dyn + (t % STAGES) * STW + ASZ;

        uint32_t af0[MI][4], bf0[NI][2], af1[MI][4], bf1[NI][2];
        LDF(sa, sb, Bs, 0, af0, bf0);
#pragma unroll
        for (int s = 0; s < NSTEP; s++) {
            if (s + 1 < NSTEP) {
                if ((s & 1) == 0) LDF(sa, sb, Bs, (s + 1) * 8, af1, bf1);
                else              LDF(sa, sb, Bs, (s + 1) * 8, af0, bf0);
            }
            if ((s & 1) == 0) MMAS(af0, bf0);
            else              MMAS(af1, bf1);
        }
        __syncthreads();
    }

    if (MODE == 7) {
        float rmax[MI][2], rsum[MI][2];
#pragma unroll
        for (int mi = 0; mi < MI; mi++)
#pragma unroll
            for (int half = 0; half < 2; half++) {
                float m = -3.4e38f;
#pragma unroll
                for (int ni = 0; ni < NI; ni++)
                    m = fmaxf(m, fmaxf(acc[mi][ni][2 * half], acc[mi][ni][2 * half + 1]));
                m = fmaxf(m, __shfl_xor_sync(~0u, m, 1));
                m = fmaxf(m, __shfl_xor_sync(~0u, m, 2));
                rmax[mi][half] = m;
            }
        if (lq == 0) {
#pragma unroll
            for (int mi = 0; mi < MI; mi++)
#pragma unroll
                for (int half = 0; half < 2; half++)
                    red[(mi * 16 + tm + 8 * half) * WGN + w] = rmax[mi][half];
        }
        __syncthreads();
#pragma unroll
        for (int mi = 0; mi < MI; mi++)
#pragma unroll
            for (int half = 0; half < 2; half++) {
                float m = -3.4e38f;
#pragma unroll
                for (int ww = 0; ww < WGN; ww++)
                    m = fmaxf(m, red[(mi * 16 + tm + 8 * half) * WGN + ww]);
                rmax[mi][half] = m;
            }
        __syncthreads();
#pragma unroll
        for (int mi = 0; mi < MI; mi++)
#pragma unroll
            for (int half = 0; half < 2; half++) {
                float s = 0.f;
#pragma unroll
                for (int ni = 0; ni < NI; ni++) {
                    float e0 = __expf(acc[mi][ni][2 * half]     - rmax[mi][half]);
                    float e1 = __expf(acc[mi][ni][2 * half + 1] - rmax[mi][half]);
                    acc[mi][ni][2 * half]     = e0;
                    acc[mi][ni][2 * half + 1] = e1;
                    s += e0 + e1;
                }
                s += __shfl_xor_sync(~0u, s, 1);
                s += __shfl_xor_sync(~0u, s, 2);
                rsum[mi][half] = s;
            }
        if (lq == 0) {
#pragma unroll
            for (int mi = 0; mi < MI; mi++)
#pragma unroll
                for (int half = 0; half < 2; half++)
                    red[(mi * 16 + tm + 8 * half) * WGN + w] = rsum[mi][half];
        }
        __syncthreads();
#pragma unroll
        for (int mi = 0; mi < MI; mi++)
#pragma unroll
            for (int half = 0; half < 2; half++) {
                float s = 0.f;
#pragma unroll
                for (int ww = 0; ww < WGN; ww++)
                    s += red[(mi * 16 + tm + 8 * half) * WGN + ww];
                rsum[mi][half] = 1.f / s;
            }
#pragma unroll
        for (int mi = 0; mi < MI; mi++) {
#pragma unroll
            for (int ni = 0; ni < NI; ni++) {
                int c = colBase + wn * WN + ni * 8 + 2 * lq;
#pragma unroll
                for (int half = 0; half < 2; half++) {
                    int r = rowBase + mi * 16 + tm + 8 * half;
                    float2 v = make_float2(rtf(acc[mi][ni][2 * half] * rsum[mi][half]),
                                           rtf(acc[mi][ni][2 * half + 1] * rsum[mi][half]));
                    *(float2*)&C[(long long)r * ldc + c] = v;
                }
            }
        }
        return;
    }

#pragma unroll
    for (int mi = 0; mi < MI; mi++) {
        int rBase = rowBase + wm * WM + mi * 16 + tm;
#pragma unroll
        for (int ni = 0; ni < NI; ni++) {
            int c = colBase + wn * WN + ni * 8 + 2 * lq;
#pragma unroll
            for (int half = 0; half < 2; half++) {
                int r = rBase + 8 * half;
                float2 v = make_float2(acc[mi][ni][2 * half], acc[mi][ni][2 * half + 1]);
                if (MODE == 0) {
                    v.x *= alpha; v.y *= alpha;
                    if (RND) { v.x = rtf(v.x); v.y = rtf(v.y); }
                    *(float2*)&C[(long long)r * ldc + c] = v;
                } else if (MODE == 2) {
                    v.x = (r == c     ? dval : 0.f) - v.x;
                    v.y = (r == c + 1 ? dval : 0.f) - v.y;
                    if (RND) { v.x = rtf(v.x); v.y = rtf(v.y); }
                    *(float2*)&C[(long long)r * ldc + c] = v;
                } else if (MODE == 3) {
                    float2 v1 = v;
                    if (RND) { v1.x = rtf(v1.x); v1.y = rtf(v1.y); }
                    *(float2*)&C[(long long)r * ldc + c] = v1;
                    float2 v2;
                    v2.x = (r == c     ? dval : 0.f) - v.x;
                    v2.y = (r == c + 1 ? dval : 0.f) - v.y;
                    if (RND) { v2.x = rtf(v2.x); v2.y = rtf(v2.y); }
                    *(float2*)&C2[(long long)r * ldc + c] = v2;
                } else if (MODE == 4) {
                    v.x += bias[c]; v.y += bias[c + 1];
                    *(float2*)&C[(long long)r * ldc + c] = v;
                } else if (MODE == 5) {
                    int b = r >> 12, n = r & 4095;
                    int part = c >> 9, h = (c >> 6) & 7, d = c & 63;
                    if (part == 0) { v.x *= 0.125f; v.y *= 0.125f; }
                    v.x = rtf(v.x); v.y = rtf(v.y);
                    float* dst = (part == 0) ? oq : ((part == 1) ? okk : ov);
                    *(float2*)&dst[((((long long)(b * 8 + h)) << 12) + n) * 64 + d] = v;
                } else { // 6: accumulate onto conv already in 'of'
                    int b = bz >> 3, h = bz & 7;
                    long long oidx = ((long long)(b * 4096 + r)) * 512 + h * 64 + c;
                    float2 prev = *(float2*)&C[oidx];
                    v.x = rtf(v.x + prev.x);
                    v.y = rtf(v.y + prev.y);
                    *(float2*)&C[oidx] = v;
                }
            }
        }
    }
}

static inline int smem_bytes(int BM, int BN, int TRANSB, int MODE, int WGN,
                             int BK, int STAGES) {
    int ASZ = BM * (BK + 4);
    int BSZ = TRANSB ? BN * (BK + 4) : BK * (BN + 8);
    int b = STAGES * (ASZ + BSZ) * 4;
    if (MODE == 7) b += BM * WGN * 4;
    return b;
}

// ---------------- split-K reduction ----------------------------------------------
__global__ void reduce4(const float* __restrict__ p, float* __restrict__ out)
{
    long long t = (long long)blockIdx.x * 256 + threadIdx.x;
    int bh = (int)(t >> 14);
    int e  = (int)(t & 16383);
    const float* pp = p + ((long long)bh * 4) * 16384 + e;
    out[t] = rtf(pp[0] + pp[16384] + pp[2 * 16384] + pp[3 * 16384]);
}

// ---------------- landmarks ---------------------------------------------------
__global__ void landmarks_kernel(const float* __restrict__ q, const float* __restrict__ k,
                                 float* __restrict__ qlm, float* __restrict__ klm)
{
    int idx = blockIdx.x;
    int d = threadIdx.x;
    long long base = ((long long)idx * 16) * 64 + d;
    float sq = 0.f, sk = 0.f;
#pragma unroll
    for (int j = 0; j < 16; j++) {
        sq += q[base + j * 64];
        sk += k[base + j * 64];
    }
    qlm[(long long)idx * 64 + d] = rtf(sq * 0.0625f);
    klm[(long long)idx * 64 + d] = rtf(sk * 0.0625f);
}

// ---------------- softmax 4096 ----------------------------------------------------
__global__ void softmax4096(float* __restrict__ data)
{
    __shared__ float redm[8], reds[8];
    float4* p = (float4*)(data + ((long long)blockIdx.x << 12));
    int tid = threadIdx.x;
    float4 v[4];
#pragma unroll
    for (int i = 0; i < 4; i++) v[i] = p[tid + 256 * i];
    float m = -3.4e38f;
#pragma unroll
    for (int i = 0; i < 4; i++)
        m = fmaxf(m, fmaxf(fmaxf(v[i].x, v[i].y), fmaxf(v[i].z, v[i].w)));
#pragma unroll
    for (int s = 16; s; s >>= 1) m = fmaxf(m, __shfl_xor_sync(~0u, m, s));
    if ((tid & 31) == 0) redm[tid >> 5] = m;
    __syncthreads();
#pragma unroll
    for (int j = 0; j < 8; j++) m = fmaxf(m, redm[j]);

    float sum = 0.f;
#pragma unroll
    for (int i = 0; i < 4; i++) {
        v[i].x = __expf(v[i].x - m); v[i].y = __expf(v[i].y - m);
        v[i].z = __expf(v[i].z - m); v[i].w = __expf(v[i].w - m);
        sum += v[i].x + v[i].y + v[i].z + v[i].w;
    }
#pragma unroll
    for (int s = 16; s; s >>= 1) sum += __shfl_xor_sync(~0u, sum, s);
    if ((tid & 31) == 0) reds[tid >> 5] = sum;
    __syncthreads();
    sum = 0.f;
#pragma unroll
    for (int j = 0; j < 8; j++) sum += reds[j];
    float inv = 1.f / sum;
#pragma unroll
    for (int i = 0; i < 4; i++) {
        v[i].x = rtf(v[i].x * inv); v[i].y = rtf(v[i].y * inv);
        v[i].z = rtf(v[i].z * inv); v[i].w = rtf(v[i].w * inv);
        p[tid + 256 * i] = v[i];
    }
}

// ---------------- pinv init ----------------------------------------------------
__global__ void zero_gmax(float* gm) { gm[0] = 0.f; gm[1] = 0.f; }

__global__ void pinv_scales(const float* __restrict__ a, float* gm)
{
    __shared__ float red[256];
    int bh = blockIdx.x, tid = threadIdx.x;
    const float* A = a + ((long long)bh << 16);
    float rs = 0.f;
    for (int j = 0; j < 256; j++) rs += fabsf(A[tid * 256 + j]);
    red[tid] = rs; __syncthreads();
    for (int s = 128; s > 0; s >>= 1) {
        if (tid < s) red[tid] = fmaxf(red[tid], red[tid + s]);
        __syncthreads();
    }
    if (tid == 0) atomicMax((int*)&gm[0], __float_as_int(red[0]));
    __syncthreads();
    float cs = 0.f;
    for (int i = 0; i < 256; i++) cs += fabsf(A[i * 256 + tid]);
    red[tid] = cs; __syncthreads();
    for (int s = 128; s > 0; s >>= 1) {
        if (tid < s) red[tid] = fmaxf(red[tid], red[tid + s]);
        __syncthreads();
    }
    if (tid == 0) atomicMax((int*)&gm[1], __float_as_int(red[0]));
}

__global__ void pinv_init(const float* __restrict__ a, float* __restrict__ z,
                          const float* __restrict__ gm)
{
    long long t = (long long)blockIdx.x * 256 + threadIdx.x;
    int bh = (int)(t >> 16);
    int ij = (int)(t & 65535);
    int i = ij >> 8, j = ij & 255;
    float inv = 1.f / (gm[0] * gm[1]);
    z[((long long)bh << 16) + ij] = rtf(a[((long long)bh << 16) + (j << 8) + i] * inv);
}

// ---------------- depthwise conv (writes 'of'; MODE 6 accumulates) -------------
__global__ void conv_of(const float* __restrict__ v, const float* __restrict__ w,
                        float* __restrict__ of)
{
    long long t = (long long)blockIdx.x * 256 + threadIdx.x;
    int d = (int)(t & 63);
    long long r = t >> 6;
    int n  = (int)(r & 4095);
    int bh = (int)(r >> 12);
    int h  = bh & 7, b = bh >> 3;
    const float* vp = v + ((long long)bh << 18) + d;
    float s = 0.f;
#pragma unroll
    for (int tp = 0; tp < 33; tp++) {
        int nn = n + tp - 16;
        if (nn >= 0 && nn < 4096)
            s = fmaf(vp[(long long)nn << 6], w[h * 33 + tp], s);
    }
    of[((long long)(b * 4096 + n)) * 512 + h * 64 + d] = s;
}

// ---------------- host orchestration -------------------------------------------
extern "C" void kernel_launch(void* const* d_in, const int* in_sizes, int n_in,
                              void* d_out, int out_size)
{
    const float* x    = (const float*)d_in[0];
    const float* Wqkv = (const float*)d_in[1];
    const float* Wout = (const float*)d_in[2];
    const float* bout = (const float*)d_in[3];
    const float* rk   = (const float*)d_in[4];
    float* yout = (float*)d_out;

    float *q, *k, *v, *qlm, *klm, *s1, *a2, *s3, *z, *z2, *xz,
          *t1, *t3, *t5, *a3v, *zv, *of, *part, *gm;
    cudaGetSymbolAddress((void**)&q,   g_q);
    cudaGetSymbolAddress((void**)&k,   g_k);
    cudaGetSymbolAddress((void**)&v,   g_v);
    cudaGetSymbolAddress((void**)&qlm, g_qlm);
    cudaGetSymbolAddress((void**)&klm, g_klm);
    cudaGetSymbolAddress((void**)&s1,  g_s1);
    cudaGetSymbolAddress((void**)&a2,  g_a2);
    cudaGetSymbolAddress((void**)&s3,  g_s3);
    cudaGetSymbolAddress((void**)&z,   g_z);
    cudaGetSymbolAddress((void**)&z2,  g_z2);
    cudaGetSymbolAddress((void**)&xz,  g_xz);
    cudaGetSymbolAddress((void**)&t1,  g_t1);
    cudaGetSymbolAddress((void**)&t3,  g_t3);
    cudaGetSymbolAddress((void**)&t5,  g_t5);
    cudaGetSymbolAddress((void**)&a3v, g_a3v);
    cudaGetSymbolAddress((void**)&zv,  g_zv);
    cudaGetSymbolAddress((void**)&of,  g_of);
    cudaGetSymbolAddress((void**)&part,g_part);
    cudaGetSymbolAddress((void**)&gm,  g_gmax);

    const long long sQ  = (long long)N_ * DH_;
    const long long sLM = (long long)M_ * DH_;
    const long long sS1 = (long long)N_ * M_;
    const long long sMM = (long long)M_ * M_;

    const int smQKV = smem_bytes(128,128,0,5,4,32,3);
    const int smSM  = smem_bytes(64,256,1,7,8,16,4);
    const int smS3  = smem_bytes(128,128,1,0,4,16,4);
    const int smNS  = smem_bytes(128,128,0,0,4,32,3);   // NS back to 128x128
    const int sm64  = smem_bytes(128,64,0,0,2,32,3);
    const int smFP  = smem_bytes(128,128,0,4,4,32,3);

    static cudaStream_t sB = nullptr, sC = nullptr;
    static cudaEvent_t evF = nullptr, evC = nullptr, evV = nullptr, evJ = nullptr;
    static bool attr_done = false;
    if (!attr_done) {
        cudaFuncSetAttribute(gemm_tc<128,128,2,4,0,5,32,3,1,1,1>, cudaFuncAttributeMaxDynamicSharedMemorySize, smQKV);
        cudaFuncSetAttribute(gemm_tc<64,256,1,8,1,7,16,4>,  cudaFuncAttributeMaxDynamicSharedMemorySize, smSM);
        cudaFuncSetAttribute(gemm_tc<128,128,2,4,1,0,16,4,1,0>, cudaFuncAttributeMaxDynamicSharedMemorySize, smS3);
        cudaFuncSetAttribute(gemm_tc<128,128,2,4,0,3,32,3>, cudaFuncAttributeMaxDynamicSharedMemorySize, smNS);
        cudaFuncSetAttribute(gemm_tc<128,128,2,4,0,2,32,3>, cudaFuncAttributeMaxDynamicSharedMemorySize, smNS);
        cudaFuncSetAttribute(gemm_tc<128,128,2,4,0,0,32,3>, cudaFuncAttributeMaxDynamicSharedMemorySize, smNS);
        cudaFuncSetAttribute(gemm_tc<128,64,4,2,0,0,32,3,4,0>, cudaFuncAttributeMaxDynamicSharedMemorySize, sm64);
        cudaFuncSetAttribute(gemm_tc<128,64,4,2,0,0,32,3>, cudaFuncAttributeMaxDynamicSharedMemorySize, sm64);
        cudaFuncSetAttribute(gemm_tc<128,64,4,2,0,6,32,3>, cudaFuncAttributeMaxDynamicSharedMemorySize, sm64);
        cudaFuncSetAttribute(gemm_tc<128,128,2,4,0,4,32,3,1,1,1>, cudaFuncAttributeMaxDynamicSharedMemorySize, smFP);
        cudaStreamCreateWithFlags(&sB, cudaStreamNonBlocking);
        cudaStreamCreateWithFlags(&sC, cudaStreamNonBlocking);
        cudaEventCreateWithFlags(&evF, cudaEventDisableTiming);
        cudaEventCreateWithFlags(&evC, cudaEventDisableTiming);
        cudaEventCreateWithFlags(&evV, cudaEventDisableTiming);
        cudaEventCreateWithFlags(&evJ, cudaEventDisableTiming);
        attr_done = true;
    }

    // 1a. qkv part A: q,k columns — CVTIN reads raw x/Wqkv (no pre-round pass)
    gemm_tc<128,128,2,4,0,5,32,3,1,1,1><<<dim3(8, 128, 1), 256, smQKV>>>(
        512, x, 512, 0, Wqkv, 1536, 0,
        nullptr, 0, 0, 1.f, 0.f, nullptr, nullptr, q, k, v, 0);

    // 1b. qkv part B: v columns — overlapped on stream C
    cudaEventRecord(evC, 0);
    cudaStreamWaitEvent(sC, evC, 0);
    gemm_tc<128,128,2,4,0,5,32,3,1,1,1><<<dim3(4, 128, 1), 256, smQKV, sC>>>(
        512, x, 512, 0, Wqkv, 1536, 0,
        nullptr, 0, 0, 1.f, 0.f, nullptr, nullptr, q, k, v, 1024);
    cudaEventRecord(evV, sC);

    // 2. landmarks (needs q,k only)
    landmarks_kernel<<<BH_ * M_, DH_>>>(q, k, qlm, klm);

    // 3. attn2 (NS branch depends only on it)
    gemm_tc<64,256,1,8,1,7,16,4><<<dim3(1, 4, BH_), 256, smSM>>>(
        64, qlm, 64, sLM, klm, 64, sLM,
        a2, 256, sMM, 1.f, 0.f, nullptr, nullptr, nullptr, nullptr, nullptr, 0);

    // ---- fork: side stream B runs pinv + Newton-Schulz (proven 128x128 tiles)
    cudaEventRecord(evF, 0);
    cudaStreamWaitEvent(sB, evF, 0);

    zero_gmax<<<1, 1, 0, sB>>>(gm);
    pinv_scales<<<BH_, 256, 0, sB>>>(a2, gm);
    pinv_init<<<(BH_ * M_ * M_) / 256, 256, 0, sB>>>(a2, z, gm);

    float* za = z;
    float* zb = z2;
    for (int it = 0; it < 6; it++) {
        gemm_tc<128,128,2,4,0,3,32,3><<<dim3(2, 2, BH_), 256, smNS, sB>>>(
            256, a2, 256, sMM, za, 256, sMM,
            xz, 256, sMM, 1.f, 7.f, t1, nullptr, nullptr, nullptr, nullptr, 0);
        gemm_tc<128,128,2,4,0,2,32,3><<<dim3(2, 2, BH_), 256, smNS, sB>>>(
            256, xz, 256, sMM, t1, 256, sMM,
            t3, 256, sMM, 1.f, 15.f, nullptr, nullptr, nullptr, nullptr, nullptr, 0);
        gemm_tc<128,128,2,4,0,2,32,3><<<dim3(2, 2, BH_), 256, smNS, sB>>>(
            256, xz, 256, sMM, t3, 256, sMM,
            t5, 256, sMM, 1.f, 13.f, nullptr, nullptr, nullptr, nullptr, nullptr, 0);
        gemm_tc<128,128,2,4,0,0,32,3><<<dim3(2, 2, BH_), 256, smNS, sB>>>(
            256, za, 256, sMM, t5, 256, sMM,
            zb, 256, sMM, 0.25f, 0.f, nullptr, nullptr, nullptr, nullptr, nullptr, 0);
        float* sw = za; za = zb; zb = sw;
    }
    cudaEventRecord(evJ, sB);

    // ---- main stream: independent attention branch ----
    gemm_tc<64,256,1,8,1,7,16,4><<<dim3(1, 64, BH_), 256, smSM>>>(
        64, q, 64, sQ, klm, 64, sLM,
        s1, 256, sS1, 1.f, 0.f, nullptr, nullptr, nullptr, nullptr, nullptr, 0);

    gemm_tc<128,128,2,4,1,0,16,4,1,0><<<dim3(32, 2, BH_), 256, smS3>>>(
        64, qlm, 64, sLM, k, 64, sQ,
        s3, 4096, (long long)M_ * N_, 1.f, 0.f, nullptr, nullptr, nullptr, nullptr, nullptr, 0);
    softmax4096<<<BH_ * M_, 256>>>(s3);

    // v-consumers wait on qkv part B
    cudaStreamWaitEvent(0, evV, 0);

    conv_of<<<(BH_ * N_ * DH_) / 256, 256>>>(v, rk, of);

    gemm_tc<128,64,4,2,0,0,32,3,4,0><<<dim3(1, 2, BH_ * 4), 256, sm64>>>(
        1024, s3, 4096, (long long)M_ * N_, v, 64, sQ,
        part, 64, sLM, 1.f, 0.f, nullptr, nullptr, nullptr, nullptr, nullptr, 0);
    reduce4<<<(BH_ * M_ * DH_) / 256, 256>>>(part, a3v);

    // ---- join with NS ----
    cudaStreamWaitEvent(0, evJ, 0);

    gemm_tc<128,64,4,2,0,0,32,3><<<dim3(1, 2, BH_), 256, sm64>>>(
        256, z, 256, sMM, a3v, 64, sLM,
        zv, 64, sLM, 1.f, 0.f, nullptr, nullptr, nullptr, nullptr, nullptr, 0);

    gemm_tc<128,64,4,2,0,6,32,3><<<dim3(1, 32, BH_), 256, sm64>>>(
        256, s1, 256, sS1, zv, 64, sLM,
        of, 0, 0, 1.f, 0.f, nullptr, nullptr, nullptr, nullptr, nullptr, 0);

    // final projection: CVTIN reads raw Wout ('of' already tf32; rounding idempotent)
    gemm_tc<128,128,2,4,0,4,32,3,1,1,1><<<dim3(4, 128, 1), 256, smFP>>>(
        512, of, 512, 0, Wout, 512, 0,
        yout, 512, 0, 1.f, 0.f, nullptr, bout, nullptr, nullptr, nullptr, 0);
}

// round 17
// speedup vs baseline: 1.0421x; 1.0336x over previous
#include <cuda_runtime.h>
#include <stdint.h>
#include <math.h>

#define B_   4
#define N_   4096
#define DIM_ 512
#define H_   8
#define DH_  64
#define M_   256
#define BH_  32

// ---------------- scratch ----------------------------------------------------
__device__ float g_x  [B_*N_*DIM_];
__device__ float g_wq [DIM_*3*H_*DH_];
__device__ float g_wo [H_*DH_*DIM_];
__device__ float g_q  [BH_*N_*DH_];
__device__ float g_k  [BH_*N_*DH_];
__device__ float g_v  [BH_*N_*DH_];
__device__ float g_qlm[BH_*M_*DH_];
__device__ float g_klm[BH_*M_*DH_];
__device__ float g_s1 [BH_*N_*M_];
__device__ float g_a2 [BH_*M_*M_];
__device__ float g_s3 [BH_*M_*N_];
__device__ float g_z  [BH_*M_*M_];
__device__ float g_z2 [BH_*M_*M_];
__device__ float g_xz [BH_*M_*M_];
__device__ float g_xz2[BH_*M_*M_];
__device__ float g_t1 [BH_*M_*M_];
__device__ float g_t3 [BH_*M_*M_];
__device__ float g_t5 [BH_*M_*M_];
__device__ float g_a3v[BH_*M_*DH_];
__device__ float g_zv [BH_*M_*DH_];
__device__ float g_of [B_*N_*DIM_];
__device__ float g_part[4*BH_*M_*DH_];
__device__ float g_gmax[2];

// ---------------- tf32 helpers -----------------------------------------------
__device__ __forceinline__ uint32_t f2tf(float f) {
    uint32_t u; asm("cvt.rna.tf32.f32 %0, %1;" : "=r"(u) : "f"(f)); return u;
}
__device__ __forceinline__ float rtf(float f) { return __uint_as_float(f2tf(f)); }

__device__ __forceinline__ void mma_tf32(float c[4],
    uint32_t a0, uint32_t a1, uint32_t a2, uint32_t a3, uint32_t b0, uint32_t b1)
{
    asm("mma.sync.aligned.m16n8k8.row.col.f32.tf32.tf32.f32 "
        "{%0,%1,%2,%3}, {%4,%5,%6,%7}, {%8,%9}, {%0,%1,%2,%3};"
        : "+f"(c[0]), "+f"(c[1]), "+f"(c[2]), "+f"(c[3])
        : "r"(a0), "r"(a1), "r"(a2), "r"(a3), "r"(b0), "r"(b1));
}

__device__ __forceinline__ void ldsm_x4(uint32_t addr, uint32_t r[4]) {
    asm volatile("ldmatrix.sync.aligned.m8n8.x4.b16 {%0,%1,%2,%3}, [%4];"
        : "=r"(r[0]), "=r"(r[1]), "=r"(r[2]), "=r"(r[3]) : "r"(addr));
}

__device__ __forceinline__ void cp16(uint32_t smem, const void* gmem) {
    asm volatile("cp.async.cg.shared.global [%0], [%1], 16;\n"
                 :: "r"(smem), "l"(gmem));
}
__device__ __forceinline__ void cp_commit() {
    asm volatile("cp.async.commit_group;\n" ::: "memory");
}
template<int N>
__device__ __forceinline__ void cp_waitg() {
    asm volatile("cp.async.wait_group %0;\n" :: "n"(N) : "memory");
}

// ---------------- pre-round inputs ---------------------------------------------
__global__ void round_copy(const float* __restrict__ in, float* __restrict__ out)
{
    long long t = (long long)blockIdx.x * 256 + threadIdx.x;
    out[t] = rtf(in[t]);
}

// ---------------- tensor-core batched GEMM (cp.async + ldmatrix fragments) -----
// MODE: 0: alpha*acc   2: dval*I - acc   3: C=acc, C2=dval*I-acc
//       4: acc + bias[col] (not rounded)  5: qkv scatter (q scaled 0.125)
//       6: ACCUMULATE into [b,n,h,d] 'of' layout   7: fused row softmax (WGM=1)
//       8: dual NS update: bz=[0,64), half=bz>>5, bh=bz&31;
//          half0: C = rtf(0.25*acc) (A operand)            [Z' = 0.25 Z t5]
//          half1: oq = rtf(0.25*acc), okk = rtf(7I - oq)   [Y' = 0.25 Y t5, A=C2]
template<int BM, int BN, int WGM, int WGN, int TRANSB, int MODE,
         int BK = 16, int STAGES = 4, int SPLITK = 1, int RND = 1>
__global__ void __launch_bounds__(256, 2)
gemm_tc(int K,
        const float* __restrict__ A,  int lda, long long sA,
        const float* __restrict__ Bg, int ldb, long long sB,
        float* __restrict__ C, int ldc, long long sC,
        float alpha, float dval,
        float* __restrict__ C2, const float* __restrict__ bias,
        float* __restrict__ oq, float* __restrict__ okk, float* __restrict__ ov,
        int colOff)
{
    constexpr int WM = BM / WGM, WN = BN / WGN;
    constexpr int MI = WM / 16,  NI = WN / 8;
    constexpr int NSTEP = BK / 8;
    constexpr int SAW = BK + 4;
    constexpr int SBW = TRANSB ? (BK + 4) : (BN + 8);
    constexpr int ASZ = BM * SAW;
    constexpr int BSZ = TRANSB ? (BN * SAW) : (BK * SBW);
    constexpr int STW = ASZ + BSZ;
    constexpr int CPR = BK / 4;
    constexpr int RPI = 256 / CPR;
    constexpr int A_IT  = BM / RPI;
    constexpr int B1_IT = BN / RPI;
    constexpr int NB4   = BN / 4;
    constexpr int B0_RS = 256 / NB4;
    constexpr int B0_IT = BK / B0_RS;

    extern __shared__ __align__(16) float dyn[];
    float* red = dyn + STAGES * STW;

    const int bz = blockIdx.z;
    int bh, ks = 0, half = 0;
    if (MODE == 8) {
        half = bz >> 5; bh = bz & 31;
        if (half) A = C2;        // Y operand
    } else {
        bh = bz / SPLITK; ks = bz % SPLITK;
    }
    A  += (long long)bh * sA + (long long)ks * K;
    Bg += (long long)bh * sB + (TRANSB ? (long long)ks * K
                                       : (long long)ks * K * ldb);
    if (MODE != 5 && MODE != 6 && MODE != 8) C += (long long)bz * sC;
    if (MODE == 3) C2 += (long long)bz * sC;

    const int tid = threadIdx.x;
    const int rowBase = blockIdx.y * BM;
    const int colBase = blockIdx.x * BN + colOff;
    const int w = tid >> 5, lane = tid & 31;
    const int wm = w / WGN, wn = w % WGN;
    const int tm = lane >> 2, lq = lane & 3;
    const int lrow = lane & 15;
    const int lhi  = (lane >> 4) & 1;

    float acc[MI][NI][4];
#pragma unroll
    for (int mi = 0; mi < MI; mi++)
#pragma unroll
        for (int ni = 0; ni < NI; ni++)
#pragma unroll
            for (int r = 0; r < 4; r++) acc[mi][ni][r] = 0.f;

    const int a_r = tid / CPR, a_c = (tid % CPR) * 4;
    const int b0k = tid / NB4, b0n = (tid % NB4) * 4;

    const uint32_t dynb = (uint32_t)__cvta_generic_to_shared(dyn);

    auto LOADG = [&](int kt, int buf) {
        uint32_t sa = dynb + buf * (STW * 4);
        uint32_t sb = sa + ASZ * 4;
#pragma unroll
        for (int i = 0; i < A_IT; i++) {
            int r = a_r + RPI * i;
            cp16(sa + (r * SAW + a_c) * 4,
                 A + (long long)(rowBase + r) * lda + kt + a_c);
        }
        if (TRANSB == 0) {
#pragma unroll
            for (int i = 0; i < B0_IT; i++) {
                int k = b0k + B0_RS * i;
                cp16(sb + (k * SBW + b0n) * 4,
                     Bg + (long long)(kt + k) * ldb + colBase + b0n);
            }
        } else {
#pragma unroll
            for (int i = 0; i < B1_IT; i++) {
                int r = a_r + RPI * i;
                cp16(sb + (r * SAW + a_c) * 4,
                     Bg + (long long)(colBase + r) * ldb + kt + a_c);
            }
        }
    };

    auto LDF = [&](uint32_t sa, uint32_t sb, const float* Bs, int kk,
                   uint32_t (*af)[4], uint32_t (*bf)[2]) {
#pragma unroll
        for (int mi = 0; mi < MI; mi++) {
            uint32_t a = sa + (uint32_t)(((wm * WM + mi * 16 + lrow) * SAW + kk) << 2)
                            + (lhi << 4);
            ldsm_x4(a, af[mi]);
        }
        if (TRANSB == 1) {
#pragma unroll
            for (int p = 0; p < NI / 2; p++) {
                uint32_t b = sb + (uint32_t)(((wn * WN + p * 16 + lrow) * SAW + kk) << 2)
                                + (lhi << 4);
                uint32_t r[4];
                ldsm_x4(b, r);
                bf[2 * p][0]     = r[0];
                bf[2 * p + 1][0] = r[1];
                bf[2 * p][1]     = r[2];
                bf[2 * p + 1][1] = r[3];
            }
        } else {
            const int kq = kk + lq;
#pragma unroll
            for (int ni = 0; ni < NI; ni++) {
                int n = wn * WN + ni * 8 + tm;
                bf[ni][0] = __float_as_uint(Bs[ kq      * SBW + n]);
                bf[ni][1] = __float_as_uint(Bs[(kq + 4) * SBW + n]);
            }
        }
    };

    auto MMAS = [&](uint32_t (*af)[4], uint32_t (*bf)[2]) {
#pragma unroll
        for (int mi = 0; mi < MI; mi++)
#pragma unroll
            for (int ni = 0; ni < NI; ni++)
                mma_tf32(acc[mi][ni], af[mi][0], af[mi][1], af[mi][2], af[mi][3],
                         bf[ni][0], bf[ni][1]);
    };

    const int T = K / BK;
#pragma unroll
    for (int s = 0; s < STAGES - 1; s++) { LOADG(s * BK, s); cp_commit(); }

    for (int t = 0; t < T; t++) {
        cp_waitg<STAGES - 2>();
        __syncthreads();
        if (t + STAGES - 1 < T) LOADG((t + STAGES - 1) * BK, (t + STAGES - 1) % STAGES);
        cp_commit();

        const uint32_t sa = dynb + (t % STAGES) * (STW * 4);
        const uint32_t sb = sa + ASZ * 4;
        const float* Bs = dyn + (t % STAGES) * STW + ASZ;

        uint32_t af0[MI][4], bf0[NI][2], af1[MI][4], bf1[NI][2];
        LDF(sa, sb, Bs, 0, af0, bf0);
#pragma unroll
        for (int s = 0; s < NSTEP; s++) {
            if (s + 1 < NSTEP) {
                if ((s & 1) == 0) LDF(sa, sb, Bs, (s + 1) * 8, af1, bf1);
                else              LDF(sa, sb, Bs, (s + 1) * 8, af0, bf0);
            }
            if ((s & 1) == 0) MMAS(af0, bf0);
            else              MMAS(af1, bf1);
        }
        __syncthreads();
    }

    if (MODE == 7) {
        float rmax[MI][2], rsum[MI][2];
#pragma unroll
        for (int mi = 0; mi < MI; mi++)
#pragma unroll
            for (int half2 = 0; half2 < 2; half2++) {
                float m = -3.4e38f;
#pragma unroll
                for (int ni = 0; ni < NI; ni++)
                    m = fmaxf(m, fmaxf(acc[mi][ni][2 * half2], acc[mi][ni][2 * half2 + 1]));
                m = fmaxf(m, __shfl_xor_sync(~0u, m, 1));
                m = fmaxf(m, __shfl_xor_sync(~0u, m, 2));
                rmax[mi][half2] = m;
            }
        if (lq == 0) {
#pragma unroll
            for (int mi = 0; mi < MI; mi++)
#pragma unroll
                for (int half2 = 0; half2 < 2; half2++)
                    red[(mi * 16 + tm + 8 * half2) * WGN + w] = rmax[mi][half2];
        }
        __syncthreads();
#pragma unroll
        for (int mi = 0; mi < MI; mi++)
#pragma unroll
            for (int half2 = 0; half2 < 2; half2++) {
                float m = -3.4e38f;
#pragma unroll
                for (int ww = 0; ww < WGN; ww++)
                    m = fmaxf(m, red[(mi * 16 + tm + 8 * half2) * WGN + ww]);
                rmax[mi][half2] = m;
            }
        __syncthreads();
#pragma unroll
        for (int mi = 0; mi < MI; mi++)
#pragma unroll
            for (int half2 = 0; half2 < 2; half2++) {
                float s = 0.f;
#pragma unroll
                for (int ni = 0; ni < NI; ni++) {
                    float e0 = __expf(acc[mi][ni][2 * half2]     - rmax[mi][half2]);
                    float e1 = __expf(acc[mi][ni][2 * half2 + 1] - rmax[mi][half2]);
                    acc[mi][ni][2 * half2]     = e0;
                    acc[mi][ni][2 * half2 + 1] = e1;
                    s += e0 + e1;
                }
                s += __shfl_xor_sync(~0u, s, 1);
                s += __shfl_xor_sync(~0u, s, 2);
                rsum[mi][half2] = s;
            }
        if (lq == 0) {
#pragma unroll
            for (int mi = 0; mi < MI; mi++)
#pragma unroll
                for (int half2 = 0; half2 < 2; half2++)
                    red[(mi * 16 + tm + 8 * half2) * WGN + w] = rsum[mi][half2];
        }
        __syncthreads();
#pragma unroll
        for (int mi = 0; mi < MI; mi++)
#pragma unroll
            for (int half2 = 0; half2 < 2; half2++) {
                float s = 0.f;
#pragma unroll
                for (int ww = 0; ww < WGN; ww++)
                    s += red[(mi * 16 + tm + 8 * half2) * WGN + ww];
                rsum[mi][half2] = 1.f / s;
            }
#pragma unroll
        for (int mi = 0; mi < MI; mi++) {
#pragma unroll
            for (int ni = 0; ni < NI; ni++) {
                int c = colBase + wn * WN + ni * 8 + 2 * lq;
#pragma unroll
                for (int half2 = 0; half2 < 2; half2++) {
                    int r = rowBase + mi * 16 + tm + 8 * half2;
                    float2 v = make_float2(rtf(acc[mi][ni][2 * half2] * rsum[mi][half2]),
                                           rtf(acc[mi][ni][2 * half2 + 1] * rsum[mi][half2]));
                    *(float2*)&C[(long long)r * ldc + c] = v;
                }
            }
        }
        return;
    }

#pragma unroll
    for (int mi = 0; mi < MI; mi++) {
        int rBase = rowBase + wm * WM + mi * 16 + tm;
#pragma unroll
        for (int ni = 0; ni < NI; ni++) {
            int c = colBase + wn * WN + ni * 8 + 2 * lq;
#pragma unroll
            for (int hf = 0; hf < 2; hf++) {
                int r = rBase + 8 * hf;
                float2 v = make_float2(acc[mi][ni][2 * hf], acc[mi][ni][2 * hf + 1]);
                if (MODE == 0) {
                    v.x *= alpha; v.y *= alpha;
                    if (RND) { v.x = rtf(v.x); v.y = rtf(v.y); }
                    *(float2*)&C[(long long)r * ldc + c] = v;
                } else if (MODE == 2) {
                    v.x = (r == c     ? dval : 0.f) - v.x;
                    v.y = (r == c + 1 ? dval : 0.f) - v.y;
                    if (RND) { v.x = rtf(v.x); v.y = rtf(v.y); }
                    *(float2*)&C[(long long)r * ldc + c] = v;
                } else if (MODE == 3) {
                    float2 v1 = v;
                    if (RND) { v1.x = rtf(v1.x); v1.y = rtf(v1.y); }
                    *(float2*)&C[(long long)r * ldc + c] = v1;
                    float2 v2;
                    v2.x = (r == c     ? dval : 0.f) - v.x;
                    v2.y = (r == c + 1 ? dval : 0.f) - v.y;
                    if (RND) { v2.x = rtf(v2.x); v2.y = rtf(v2.y); }
                    *(float2*)&C2[(long long)r * ldc + c] = v2;
                } else if (MODE == 4) {
                    v.x += bias[c]; v.y += bias[c + 1];
                    *(float2*)&C[(long long)r * ldc + c] = v;
                } else if (MODE == 5) {
                    int b = r >> 12, n = r & 4095;
                    int part = c >> 9, h = (c >> 6) & 7, d = c & 63;
                    if (part == 0) { v.x *= 0.125f; v.y *= 0.125f; }
                    v.x = rtf(v.x); v.y = rtf(v.y);
                    float* dst = (part == 0) ? oq : ((part == 1) ? okk : ov);
                    *(float2*)&dst[((((long long)(b * 8 + h)) << 12) + n) * 64 + d] = v;
                } else if (MODE == 8) {
                    long long base = (long long)bh * sC + (long long)r * ldc + c;
                    float2 s = make_float2(rtf(v.x * 0.25f), rtf(v.y * 0.25f));
                    if (half == 0) {
                        *(float2*)&C[base] = s;
                    } else {
                        *(float2*)&oq[base] = s;
                        float2 t;
                        t.x = rtf((r == c     ? 7.f : 0.f) - s.x);
                        t.y = rtf((r == c + 1 ? 7.f : 0.f) - s.y);
                        *(float2*)&okk[base] = t;
                    }
                } else { // 6: accumulate onto conv already in 'of'
                    int b = bz >> 3, h = bz & 7;
                    long long oidx = ((long long)(b * 4096 + r)) * 512 + h * 64 + c;
                    float2 prev = *(float2*)&C[oidx];
                    v.x = rtf(v.x + prev.x);
                    v.y = rtf(v.y + prev.y);
                    *(float2*)&C[oidx] = v;
                }
            }
        }
    }
}

static inline int smem_bytes(int BM, int BN, int TRANSB, int MODE, int WGN,
                             int BK, int STAGES) {
    int ASZ = BM * (BK + 4);
    int BSZ = TRANSB ? BN * (BK + 4) : BK * (BN + 8);
    int b = STAGES * (ASZ + BSZ) * 4;
    if (MODE == 7) b += BM * WGN * 4;
    return b;
}

// ---------------- split-K reduction ----------------------------------------------
__global__ void reduce4(const float* __restrict__ p, float* __restrict__ out)
{
    long long t = (long long)blockIdx.x * 256 + threadIdx.x;
    int bh = (int)(t >> 14);
    int e  = (int)(t & 16383);
    const float* pp = p + ((long long)bh * 4) * 16384 + e;
    out[t] = rtf(pp[0] + pp[16384] + pp[2 * 16384] + pp[3 * 16384]);
}

// ---------------- landmarks ---------------------------------------------------
__global__ void landmarks_kernel(const float* __restrict__ q, const float* __restrict__ k,
                                 float* __restrict__ qlm, float* __restrict__ klm)
{
    int idx = blockIdx.x;
    int d = threadIdx.x;
    long long base = ((long long)idx * 16) * 64 + d;
    float sq = 0.f, sk = 0.f;
#pragma unroll
    for (int j = 0; j < 16; j++) {
        sq += q[base + j * 64];
        sk += k[base + j * 64];
    }
    qlm[(long long)idx * 64 + d] = rtf(sq * 0.0625f);
    klm[(long long)idx * 64 + d] = rtf(sk * 0.0625f);
}

// ---------------- softmax 4096 ----------------------------------------------------
__global__ void softmax4096(float* __restrict__ data)
{
    __shared__ float redm[8], reds[8];
    float4* p = (float4*)(data + ((long long)blockIdx.x << 12));
    int tid = threadIdx.x;
    float4 v[4];
#pragma unroll
    for (int i = 0; i < 4; i++) v[i] = p[tid + 256 * i];
    float m = -3.4e38f;
#pragma unroll
    for (int i = 0; i < 4; i++)
        m = fmaxf(m, fmaxf(fmaxf(v[i].x, v[i].y), fmaxf(v[i].z, v[i].w)));
#pragma unroll
    for (int s = 16; s; s >>= 1) m = fmaxf(m, __shfl_xor_sync(~0u, m, s));
    if ((tid & 31) == 0) redm[tid >> 5] = m;
    __syncthreads();
#pragma unroll
    for (int j = 0; j < 8; j++) m = fmaxf(m, redm[j]);

    float sum = 0.f;
#pragma unroll
    for (int i = 0; i < 4; i++) {
        v[i].x = __expf(v[i].x - m); v[i].y = __expf(v[i].y - m);
        v[i].z = __expf(v[i].z - m); v[i].w = __expf(v[i].w - m);
        sum += v[i].x + v[i].y + v[i].z + v[i].w;
    }
#pragma unroll
    for (int s = 16; s; s >>= 1) sum += __shfl_xor_sync(~0u, sum, s);
    if ((tid & 31) == 0) reds[tid >> 5] = sum;
    __syncthreads();
    sum = 0.f;
#pragma unroll
    for (int j = 0; j < 8; j++) sum += reds[j];
    float inv = 1.f / sum;
#pragma unroll
    for (int i = 0; i < 4; i++) {
        v[i].x = rtf(v[i].x * inv); v[i].y = rtf(v[i].y * inv);
        v[i].z = rtf(v[i].z * inv); v[i].w = rtf(v[i].w * inv);
        p[tid + 256 * i] = v[i];
    }
}

// ---------------- pinv init ----------------------------------------------------
__global__ void zero_gmax(float* gm) { gm[0] = 0.f; gm[1] = 0.f; }

__global__ void pinv_scales(const float* __restrict__ a, float* gm)
{
    __shared__ float red[256];
    int bh = blockIdx.x, tid = threadIdx.x;
    const float* A = a + ((long long)bh << 16);
    float rs = 0.f;
    for (int j = 0; j < 256; j++) rs += fabsf(A[tid * 256 + j]);
    red[tid] = rs; __syncthreads();
    for (int s = 128; s > 0; s >>= 1) {
        if (tid < s) red[tid] = fmaxf(red[tid], red[tid + s]);
        __syncthreads();
    }
    if (tid == 0) atomicMax((int*)&gm[0], __float_as_int(red[0]));
    __syncthreads();
    float cs = 0.f;
    for (int i = 0; i < 256; i++) cs += fabsf(A[i * 256 + tid]);
    red[tid] = cs; __syncthreads();
    for (int s = 128; s > 0; s >>= 1) {
        if (tid < s) red[tid] = fmaxf(red[tid], red[tid + s]);
        __syncthreads();
    }
    if (tid == 0) atomicMax((int*)&gm[1], __float_as_int(red[0]));
}

__global__ void pinv_init(const float* __restrict__ a, float* __restrict__ z,
                          const float* __restrict__ gm)
{
    long long t = (long long)blockIdx.x * 256 + threadIdx.x;
    int bh = (int)(t >> 16);
    int ij = (int)(t & 65535);
    int i = ij >> 8, j = ij & 255;
    float inv = 1.f / (gm[0] * gm[1]);
    z[((long long)bh << 16) + ij] = rtf(a[((long long)bh << 16) + (j << 8) + i] * inv);
}

// ---------------- depthwise conv (writes 'of'; MODE 6 accumulates) -------------
__global__ void conv_of(const float* __restrict__ v, const float* __restrict__ w,
                        float* __restrict__ of)
{
    long long t = (long long)blockIdx.x * 256 + threadIdx.x;
    int d = (int)(t & 63);
    long long r = t >> 6;
    int n  = (int)(r & 4095);
    int bh = (int)(r >> 12);
    int h  = bh & 7, b = bh >> 3;
    const float* vp = v + ((long long)bh << 18) + d;
    float s = 0.f;
#pragma unroll
    for (int tp = 0; tp < 33; tp++) {
        int nn = n + tp - 16;
        if (nn >= 0 && nn < 4096)
            s = fmaf(vp[(long long)nn << 6], w[h * 33 + tp], s);
    }
    of[((long long)(b * 4096 + n)) * 512 + h * 64 + d] = s;
}

// ---------------- host orchestration -------------------------------------------
extern "C" void kernel_launch(void* const* d_in, const int* in_sizes, int n_in,
                              void* d_out, int out_size)
{
    const float* x    = (const float*)d_in[0];
    const float* Wqkv = (const float*)d_in[1];
    const float* Wout = (const float*)d_in[2];
    const float* bout = (const float*)d_in[3];
    const float* rk   = (const float*)d_in[4];
    float* yout = (float*)d_out;

    float *xr, *wq, *wo, *q, *k, *v, *qlm, *klm, *s1, *a2, *s3, *z, *z2,
          *xz, *xz2, *t1, *t3, *t5, *a3v, *zv, *of, *part, *gm;
    cudaGetSymbolAddress((void**)&xr,  g_x);
    cudaGetSymbolAddress((void**)&wq,  g_wq);
    cudaGetSymbolAddress((void**)&wo,  g_wo);
    cudaGetSymbolAddress((void**)&q,   g_q);
    cudaGetSymbolAddress((void**)&k,   g_k);
    cudaGetSymbolAddress((void**)&v,   g_v);
    cudaGetSymbolAddress((void**)&qlm, g_qlm);
    cudaGetSymbolAddress((void**)&klm, g_klm);
    cudaGetSymbolAddress((void**)&s1,  g_s1);
    cudaGetSymbolAddress((void**)&a2,  g_a2);
    cudaGetSymbolAddress((void**)&s3,  g_s3);
    cudaGetSymbolAddress((void**)&z,   g_z);
    cudaGetSymbolAddress((void**)&z2,  g_z2);
    cudaGetSymbolAddress((void**)&xz,  g_xz);
    cudaGetSymbolAddress((void**)&xz2, g_xz2);
    cudaGetSymbolAddress((void**)&t1,  g_t1);
    cudaGetSymbolAddress((void**)&t3,  g_t3);
    cudaGetSymbolAddress((void**)&t5,  g_t5);
    cudaGetSymbolAddress((void**)&a3v, g_a3v);
    cudaGetSymbolAddress((void**)&zv,  g_zv);
    cudaGetSymbolAddress((void**)&of,  g_of);
    cudaGetSymbolAddress((void**)&part,g_part);
    cudaGetSymbolAddress((void**)&gm,  g_gmax);

    const long long sQ  = (long long)N_ * DH_;
    const long long sLM = (long long)M_ * DH_;
    const long long sS1 = (long long)N_ * M_;
    const long long sMM = (long long)M_ * M_;

    const int smQKV = smem_bytes(128,128,0,5,4,32,3);
    const int smSM  = smem_bytes(64,256,1,7,8,16,4);
    const int smS3  = smem_bytes(128,128,1,0,4,16,4);
    const int smNS  = smem_bytes(128,128,0,0,4,32,3);
    const int sm64  = smem_bytes(128,64,0,0,2,32,3);
    const int smFP  = smem_bytes(128,128,0,4,4,32,3);

    static cudaStream_t sB = nullptr, sC = nullptr;
    static cudaEvent_t evF = nullptr, evC = nullptr, evV = nullptr, evJ = nullptr;
    static bool attr_done = false;
    if (!attr_done) {
        cudaFuncSetAttribute(gemm_tc<128,128,2,4,0,5,32,3>, cudaFuncAttributeMaxDynamicSharedMemorySize, smQKV);
        cudaFuncSetAttribute(gemm_tc<64,256,1,8,1,7,16,4>,  cudaFuncAttributeMaxDynamicSharedMemorySize, smSM);
        cudaFuncSetAttribute(gemm_tc<128,128,2,4,1,0,16,4,1,0>, cudaFuncAttributeMaxDynamicSharedMemorySize, smS3);
        cudaFuncSetAttribute(gemm_tc<128,128,2,4,0,3,32,3>, cudaFuncAttributeMaxDynamicSharedMemorySize, smNS);
        cudaFuncSetAttribute(gemm_tc<128,128,2,4,0,2,32,3>, cudaFuncAttributeMaxDynamicSharedMemorySize, smNS);
        cudaFuncSetAttribute(gemm_tc<128,128,2,4,0,0,32,3>, cudaFuncAttributeMaxDynamicSharedMemorySize, smNS);
        cudaFuncSetAttribute(gemm_tc<128,128,2,4,0,8,32,3>, cudaFuncAttributeMaxDynamicSharedMemorySize, smNS);
        cudaFuncSetAttribute(gemm_tc<128,64,4,2,0,0,32,3,4,0>, cudaFuncAttributeMaxDynamicSharedMemorySize, sm64);
        cudaFuncSetAttribute(gemm_tc<128,64,4,2,0,0,32,3>, cudaFuncAttributeMaxDynamicSharedMemorySize, sm64);
        cudaFuncSetAttribute(gemm_tc<128,64,4,2,0,6,32,3>, cudaFuncAttributeMaxDynamicSharedMemorySize, sm64);
        cudaFuncSetAttribute(gemm_tc<128,128,2,4,0,4,32,3>, cudaFuncAttributeMaxDynamicSharedMemorySize, smFP);
        cudaStreamCreateWithFlags(&sB, cudaStreamNonBlocking);
        cudaStreamCreateWithFlags(&sC, cudaStreamNonBlocking);
        cudaEventCreateWithFlags(&evF, cudaEventDisableTiming);
        cudaEventCreateWithFlags(&evC, cudaEventDisableTiming);
        cudaEventCreateWithFlags(&evV, cudaEventDisableTiming);
        cudaEventCreateWithFlags(&evJ, cudaEventDisableTiming);
        attr_done = true;
    }

    // 0. pre-round harness inputs to tf32 (round-14 proven prologue)
    round_copy<<<(B_*N_*DIM_) / 256, 256>>>(x, xr);
    round_copy<<<(DIM_*3*H_*DH_) / 256, 256>>>(Wqkv, wq);

    // 1a. qkv part A: q,k columns — critical path
    gemm_tc<128,128,2,4,0,5,32,3><<<dim3(8, 128, 1), 256, smQKV>>>(
        512, xr, 512, 0, wq, 1536, 0,
        nullptr, 0, 0, 1.f, 0.f, nullptr, nullptr, q, k, v, 0);

    // 1b. qkv part B: v columns — overlapped on stream C
    cudaEventRecord(evC, 0);
    cudaStreamWaitEvent(sC, evC, 0);
    gemm_tc<128,128,2,4,0,5,32,3><<<dim3(4, 128, 1), 256, smQKV, sC>>>(
        512, xr, 512, 0, wq, 1536, 0,
        nullptr, 0, 0, 1.f, 0.f, nullptr, nullptr, q, k, v, 1024);
    cudaEventRecord(evV, sC);

    // 2. landmarks (needs q,k only)
    landmarks_kernel<<<BH_ * M_, DH_>>>(q, k, qlm, klm);

    // 3. attn2 (NS branch depends only on it)
    gemm_tc<64,256,1,8,1,7,16,4><<<dim3(1, 4, BH_), 256, smSM>>>(
        64, qlm, 64, sLM, klm, 64, sLM,
        a2, 256, sMM, 1.f, 0.f, nullptr, nullptr, nullptr, nullptr, nullptr, 0);

    // ---- fork: side stream B runs pinv + shortened Newton-Schulz chain ----
    cudaEventRecord(evF, 0);
    cudaStreamWaitEvent(sB, evF, 0);

    zero_gmax<<<1, 1, 0, sB>>>(gm);
    pinv_scales<<<BH_, 256, 0, sB>>>(a2, gm);
    pinv_init<<<(BH_ * M_ * M_) / 256, 256, 0, sB>>>(a2, z, gm);

    float* za = z;   float* zb = z2;
    float* ya = xz;  float* yb = xz2;

    // Y_0 = a2 @ Z_0 ; t1 = 7I - Y_0
    gemm_tc<128,128,2,4,0,3,32,3><<<dim3(2, 2, BH_), 256, smNS, sB>>>(
        256, a2, 256, sMM, za, 256, sMM,
        ya, 256, sMM, 1.f, 7.f, t1, nullptr, nullptr, nullptr, nullptr, 0);

    for (int it = 0; it < 6; it++) {
        gemm_tc<128,128,2,4,0,2,32,3><<<dim3(2, 2, BH_), 256, smNS, sB>>>(
            256, ya, 256, sMM, t1, 256, sMM,
            t3, 256, sMM, 1.f, 15.f, nullptr, nullptr, nullptr, nullptr, nullptr, 0);
        gemm_tc<128,128,2,4,0,2,32,3><<<dim3(2, 2, BH_), 256, smNS, sB>>>(
            256, ya, 256, sMM, t3, 256, sMM,
            t5, 256, sMM, 1.f, 13.f, nullptr, nullptr, nullptr, nullptr, nullptr, 0);
        if (it < 5) {
            // dual update: Z' = 0.25 Z t5 (half0) ; Y' = 0.25 Y t5, t1' = 7I - Y' (half1)
            gemm_tc<128,128,2,4,0,8,32,3><<<dim3(2, 2, 2 * BH_), 256, smNS, sB>>>(
                256, za, 256, sMM, t5, 256, sMM,
                zb, 256, sMM, 0.25f, 0.f, ya, nullptr, yb, t1, nullptr, 0);
            float* sw = za; za = zb; zb = sw;
            sw = ya; ya = yb; yb = sw;
        } else {
            gemm_tc<128,128,2,4,0,0,32,3><<<dim3(2, 2, BH_), 256, smNS, sB>>>(
                256, za, 256, sMM, t5, 256, sMM,
                zb, 256, sMM, 0.25f, 0.f, nullptr, nullptr, nullptr, nullptr, nullptr, 0);
            za = zb;
        }
    }
    cudaEventRecord(evJ, sB);

    // ---- main stream: independent attention branch ----
    round_copy<<<(H_*DH_*DIM_) / 256, 256>>>(Wout, wo);

    gemm_tc<64,256,1,8,1,7,16,4><<<dim3(1, 64, BH_), 256, smSM>>>(
        64, q, 64, sQ, klm, 64, sLM,
        s1, 256, sS1, 1.f, 0.f, nullptr, nullptr, nullptr, nullptr, nullptr, 0);

    gemm_tc<128,128,2,4,1,0,16,4,1,0><<<dim3(32, 2, BH_), 256, smS3>>>(
        64, qlm, 64, sLM, k, 64, sQ,
        s3, 4096, (long long)M_ * N_, 1.f, 0.f, nullptr, nullptr, nullptr, nullptr, nullptr, 0);
    softmax4096<<<BH_ * M_, 256>>>(s3);

    // v-consumers wait on qkv part B
    cudaStreamWaitEvent(0, evV, 0);

    conv_of<<<(BH_ * N_ * DH_) / 256, 256>>>(v, rk, of);

    gemm_tc<128,64,4,2,0,0,32,3,4,0><<<dim3(1, 2, BH_ * 4), 256, sm64>>>(
        1024, s3, 4096, (long long)M_ * N_, v, 64, sQ,
        part, 64, sLM, 1.f, 0.f, nullptr, nullptr, nullptr, nullptr, nullptr, 0);
    reduce4<<<(BH_ * M_ * DH_) / 256, 256>>>(part, a3v);

    // ---- join with NS ----
    cudaStreamWaitEvent(0, evJ, 0);

    // zv = Z_final @ a3v  (Z_final lands in g_z)
    gemm_tc<128,64,4,2,0,0,32,3><<<dim3(1, 2, BH_), 256, sm64>>>(
        256, za, 256, sMM, a3v, 64, sLM,
        zv, 64, sLM, 1.f, 0.f, nullptr, nullptr, nullptr, nullptr, nullptr, 0);

    gemm_tc<128,64,4,2,0,6,32,3><<<dim3(1, 32, BH_), 256, sm64>>>(
        256, s1, 256, sS1, zv, 64, sLM,
        of, 0, 0, 1.f, 0.f, nullptr, nullptr, nullptr, nullptr, nullptr, 0);

    gemm_tc<128,128,2,4,0,4,32,3><<<dim3(4, 128, 1), 256, smFP>>>(
        512, of, 512, 0, wo, 512, 0,
        yout, 512, 0, 1.f, 0.f, nullptr, bout, nullptr, nullptr, nullptr, 0);
}